// round 11
// baseline (speedup 1.0000x reference)
#include <cuda_runtime.h>
#include <cuda_bf16.h>
#include <math.h>

#define HW    57600
#define IMGW  240
#define PW    244
#define PH    242
#define PHW   (PH * PW)      // 59048
#define LOG_MAX 4.6051701859880914f

// Scratch (allocation-free):
__device__ float    g_conv1[288 * HW];
__device__ float    g_v1[32 * HW];
__device__ unsigned g_wrep[768 * 864];
__device__ float    g_bias[288];
__device__ unsigned g_xa_hi[48 * PHW];
__device__ unsigned g_xa_lo[48 * PHW];
__device__ unsigned g_ya_hi[48 * PHW];
__device__ unsigned g_ya_lo[48 * PHW];

__device__ __forceinline__ unsigned pack_bf2(float a, float b) {
    __nv_bfloat162 h;
    h.x = __float2bfloat16_rn(a);
    h.y = __float2bfloat16_rn(b);
    return *(unsigned*)&h;
}
__device__ __forceinline__ unsigned smem_u32(const void* p) {
    return (unsigned)__cvta_generic_to_shared(p);
}
#define CP16(dst, src) asm volatile("cp.async.cg.shared.global [%0], [%1], 16;" :: "r"(dst), "l"(src))
#define CP8(dst, src)  asm volatile("cp.async.ca.shared.global [%0], [%1], 8;"  :: "r"(dst), "l"(src))
#define CP_COMMIT()    asm volatile("cp.async.commit_group;" ::: "memory")
#define CP_WAIT1()     asm volatile("cp.async.wait_group 1;" ::: "memory")

// ---- packed f32x2 helpers ----
__device__ __forceinline__ unsigned long long mul2(unsigned long long a,
                                                   unsigned long long b) {
    unsigned long long d;
    asm("mul.rn.f32x2 %0, %1, %2;" : "=l"(d) : "l"(a), "l"(b));
    return d;
}
__device__ __forceinline__ unsigned long long fma2(unsigned long long a,
                                                   unsigned long long b,
                                                   unsigned long long c) {
    unsigned long long d;
    asm("fma.rn.f32x2 %0, %1, %2, %3;" : "=l"(d) : "l"(a), "l"(b), "l"(c));
    return d;
}
__device__ __forceinline__ unsigned long long pk2(float lo, float hi) {
    unsigned long long r;
    asm("mov.b64 %0, {%1,%2};" : "=l"(r) : "f"(lo), "f"(hi));
    return r;
}
__device__ __forceinline__ float2 upk2(unsigned long long v) {
    float2 f;
    asm("mov.b64 {%0,%1}, %2;" : "=f"(f.x), "=f"(f.y) : "l"(v));
    return f;
}

// ---------------------------------------------------------------------------
// Fused prep + weight repack in ONE launch.
// ---------------------------------------------------------------------------
#define NPREP_X (48 * PHW)
#define NPREP_B (48 * (2 * PW + 4 * 240))
#define NREPACK (384 * 432)

__device__ __forceinline__ void repack_one(const float* wt, unsigned* wrep,
                                           int idx, int CoutLocal, int ocOff,
                                           int CoutTotal) {
    int o = idx % CoutLocal;
    int rem = idx / CoutLocal;
    int p = rem % 8; int rem2 = rem / 8;
    int s = rem2 % 9;
    int ch = rem2 / 9;
    int ic = ch * 16 + 2 * p;
    float v0 = wt[(o * 96 + ic) * 9 + s];
    float v1 = wt[(o * 96 + ic + 1) * 9 + s];
    __nv_bfloat16 h0 = __float2bfloat16_rn(v0);
    __nv_bfloat16 h1 = __float2bfloat16_rn(v1);
    __nv_bfloat162 hi; hi.x = h0; hi.y = h1;
    int dst = rem * CoutTotal + ocOff + o;
    wrep[dst] = *(unsigned*)&hi;
    wrep[CoutTotal * 432 + dst] =
        pack_bf2(v0 - __bfloat162float(h0), v1 - __bfloat162float(h1));
}

__global__ void prep_repack_kernel(const float* __restrict__ x,
                                   const float* __restrict__ b_in,
                                   const float* __restrict__ b_f,
                                   const float* __restrict__ w_in,
                                   const float* __restrict__ w_f,
                                   const float* __restrict__ w_out) {
    int idx = blockIdx.x * 256 + threadIdx.x;
    if (idx < NPREP_X) {
        int p = idx / PHW, rem = idx % PHW;
        int py = rem / PW, px = rem % PW;
        float v0 = 0.f, v1 = 0.f;
        if (py >= 1 && py <= 240 && px >= 1 && px <= 240) {
            int pos = (py - 1) * IMGW + (px - 1);
            v0 = x[(2 * p) * HW + pos];
            v1 = x[(2 * p + 1) * HW + pos];
        }
        __nv_bfloat16 h0 = __float2bfloat16_rn(v0);
        __nv_bfloat16 h1 = __float2bfloat16_rn(v1);
        __nv_bfloat162 hh; hh.x = h0; hh.y = h1;
        g_xa_hi[idx] = *(unsigned*)&hh;
        g_xa_lo[idx] = pack_bf2(v0 - __bfloat162float(h0), v1 - __bfloat162float(h1));
        return;
    }
    idx -= NPREP_X;
    if (idx < NPREP_B) {
        const int PER = 2 * PW + 4 * 240;
        int p = idx / PER, j = idx % PER;
        int py, px;
        if (j < 2 * PW) { py = (j / PW) ? 241 : 0; px = j % PW; }
        else {
            int k = j - 2 * PW;
            py = 1 + (k % 240);
            int c = k / 240;
            px = (c == 0) ? 0 : 240 + c;
        }
        int o = p * PHW + py * PW + px;
        g_ya_hi[o] = 0u;
        g_ya_lo[o] = 0u;
        return;
    }
    idx -= NPREP_B;
    if (idx < 288) {
        g_bias[idx] = idx < 192 ? b_in[idx] : b_f[idx - 192];
        return;
    }
    idx -= 288;
    const int T1 = 192 * 432, T2 = 96 * 432;
    if (idx < T1) { repack_one(w_in, g_wrep, idx, 192, 0, 288); return; }
    idx -= T1;
    if (idx < T2) { repack_one(w_f, g_wrep, idx, 96, 192, 288); return; }
    idx -= T2;
    if (idx < T2) repack_one(w_out, g_wrep + 2 * 288 * 432, idx, 96, 0, 96);
}

// ---------------------------------------------------------------------------
// Implicit-GEMM 3x3 conv, m16n8k16 bf16, 2-way split.
// A: cp.async double-buffered in SMEM (25.6 KB total, static).
// B: direct LDG from global (L1-cached; 55 KB/chunk working set, reused by
//    ~450 blocks) — removes 81% of cp.async LSU traffic and 4 barriers/chunk.
// ---------------------------------------------------------------------------
__global__ __launch_bounds__(256, 2) void conv3x3_mma_kernel(
    const unsigned* __restrict__ in_hi, const unsigned* __restrict__ in_lo,
    const unsigned* __restrict__ wrep, const float* __restrict__ bias,
    float* __restrict__ out, int Cout) {
    __shared__ unsigned s_a[2][3200];   // [buf][icpair*200 + y*20 + x], hi|lo halves

    const int tid = threadIdx.x;
    const int lane = tid & 31, w = tid >> 5;
    const int wm = w & 1, wn = w >> 1;
    const int x0 = blockIdx.x * 16, y0 = blockIdx.y * 8;
    const int oc_blk = blockIdx.z * 96;
    const int g = lane >> 2, t = lane & 3;
    const int wlo = Cout * 432;

    auto stage_a = [&](int ch, int buf) {
        unsigned* a_base = s_a[buf];
        for (int i = tid; i < 800; i += 256) {
            int p = i / 100, r = i % 100;
            int ly = r / 10, seg = r % 10;
            int is_lo = seg >= 5, s5 = seg - is_lo * 5;
            int lx = s5 * 4;
            const unsigned* src = (is_lo ? in_lo : in_hi) +
                                  (ch * 8 + p) * PHW + (y0 + ly) * PW + x0 + lx;
            unsigned dst = smem_u32(a_base + is_lo * 1600 + p * 200 + ly * 20 + lx);
            if (s5 < 4) CP16(dst, src);
            else        CP8(dst, src);
        }
    };

    float acc[4][3][4];
#pragma unroll
    for (int j = 0; j < 3; j++) {
        int oc = oc_blk + wn * 24 + j * 8 + 2 * t;
        float b0 = bias[oc], b1 = bias[oc + 1];
#pragma unroll
        for (int i = 0; i < 4; i++) {
            acc[i][j][0] = b0; acc[i][j][1] = b1;
            acc[i][j][2] = b0; acc[i][j][3] = b1;
        }
    }

    stage_a(0, 0);
    CP_COMMIT();

    for (int ch = 0; ch < 6; ch++) {
        if (ch < 5) stage_a(ch + 1, (ch + 1) & 1);
        CP_COMMIT();     // possibly empty group on last iter
        CP_WAIT1();      // A(ch) complete (A(ch+1) may remain in flight)
        __syncthreads();

        const unsigned* a_hi = s_a[ch & 1];
        const unsigned* a_lo = a_hi + 1600;
        // per-warp B base for this chunk: rows (ch*72 + s*8 + t), col wn*24+g
        const unsigned* brow = wrep + (ch * 72 + t) * Cout + oc_blk + wn * 24 + g;

#pragma unroll
        for (int s = 0; s < 9; s++) {
            const int dy = s / 3, dx = s % 3;
            const unsigned* b0p = brow + s * 8 * Cout;
            unsigned bh[3][2], bl[3][2];
#pragma unroll
            for (int j = 0; j < 3; j++) {
                bh[j][0] = __ldg(b0p + j * 8);
                bh[j][1] = __ldg(b0p + 4 * Cout + j * 8);
                bl[j][0] = __ldg(b0p + wlo + j * 8);
                bl[j][1] = __ldg(b0p + wlo + 4 * Cout + j * 8);
            }
#pragma unroll
            for (int i = 0; i < 4; i++) {
                int py = wm * 4 + i;
                int o00 = t * 200 + (py + dy) * 20 + g + dx;
                int o4  = o00 + 800;
                unsigned ah0 = a_hi[o00], ah1 = a_hi[o00 + 8];
                unsigned ah2 = a_hi[o4],  ah3 = a_hi[o4 + 8];
                unsigned al0 = a_lo[o00], al1 = a_lo[o00 + 8];
                unsigned al2 = a_lo[o4],  al3 = a_lo[o4 + 8];
#pragma unroll
                for (int j = 0; j < 3; j++) {
                    asm volatile(
                        "mma.sync.aligned.m16n8k16.row.col.f32.bf16.bf16.f32 "
                        "{%0,%1,%2,%3}, {%4,%5,%6,%7}, {%8,%9}, {%0,%1,%2,%3};"
                        : "+f"(acc[i][j][0]), "+f"(acc[i][j][1]),
                          "+f"(acc[i][j][2]), "+f"(acc[i][j][3])
                        : "r"(al0), "r"(al1), "r"(al2), "r"(al3),
                          "r"(bh[j][0]), "r"(bh[j][1]));
                    asm volatile(
                        "mma.sync.aligned.m16n8k16.row.col.f32.bf16.bf16.f32 "
                        "{%0,%1,%2,%3}, {%4,%5,%6,%7}, {%8,%9}, {%0,%1,%2,%3};"
                        : "+f"(acc[i][j][0]), "+f"(acc[i][j][1]),
                          "+f"(acc[i][j][2]), "+f"(acc[i][j][3])
                        : "r"(ah0), "r"(ah1), "r"(ah2), "r"(ah3),
                          "r"(bl[j][0]), "r"(bl[j][1]));
                    asm volatile(
                        "mma.sync.aligned.m16n8k16.row.col.f32.bf16.bf16.f32 "
                        "{%0,%1,%2,%3}, {%4,%5,%6,%7}, {%8,%9}, {%0,%1,%2,%3};"
                        : "+f"(acc[i][j][0]), "+f"(acc[i][j][1]),
                          "+f"(acc[i][j][2]), "+f"(acc[i][j][3])
                        : "r"(ah0), "r"(ah1), "r"(ah2), "r"(ah3),
                          "r"(bh[j][0]), "r"(bh[j][1]));
                }
            }
        }
        __syncthreads();   // all warps done with buf[ch&1] before it is restaged
    }

    const int gx0 = x0 + g;
#pragma unroll
    for (int i = 0; i < 4; i++) {
        int gy = y0 + wm * 4 + i;
#pragma unroll
        for (int j = 0; j < 3; j++) {
            int oc = oc_blk + wn * 24 + j * 8 + 2 * t;
            out[oc * HW + gy * IMGW + gx0] = acc[i][j][0];
            out[(oc + 1) * HW + gy * IMGW + gx0] = acc[i][j][1];
            out[oc * HW + gy * IMGW + gx0 + 8] = acc[i][j][2];
            out[(oc + 1) * HW + gy * IMGW + gx0 + 8] = acc[i][j][3];
        }
    }
}

__device__ __forceinline__ float4 l2n(float4 a) {
    float n = sqrtf(a.x * a.x + a.y * a.y + a.z * a.z + a.w * a.w);
    float inv = 1.f / fmaxf(n, 1e-12f);
    a.x *= inv; a.y *= inv; a.z *= inv; a.w *= inv;
    return a;
}

__device__ __forceinline__ void store_y_pair(int pair, int ppos, float a, float b) {
    __nv_bfloat16 ha = __float2bfloat16_rn(a), hb = __float2bfloat16_rn(b);
    __nv_bfloat162 hh; hh.x = ha; hh.y = hb;
    g_ya_hi[pair * PHW + ppos] = *(unsigned*)&hh;
    g_ya_lo[pair * PHW + ppos] =
        pack_bf2(a - __bfloat162float(ha), b - __bfloat162float(hb));
}

__device__ __forceinline__ void load_q(int n, int pos, float sc,
                                       unsigned long long& qxy,
                                       unsigned long long& qzw) {
    float4 q;
    q.x = g_conv1[(256 + n * 4 + 0) * HW + pos];
    q.y = g_conv1[(256 + n * 4 + 1) * HW + pos];
    q.z = g_conv1[(256 + n * 4 + 2) * HW + pos];
    q.w = g_conv1[(256 + n * 4 + 3) * HW + pos];
    q = l2n(q);
    qxy = pk2(q.x * sc, q.y * sc);
    qzw = pk2(q.z * sc, q.w * sc);
}

// ---------------------------------------------------------------------------
// Fused attention launch #1 (unchanged from R10).
// ---------------------------------------------------------------------------
__global__ __launch_bounds__(256) void attn_winrow_kernel(
    const float* __restrict__ ls, const float* __restrict__ lrls) {
    __shared__ ulonglong2 s_k2[240];
    __shared__ ulonglong2 s_v2[240];
    __shared__ float s_sc[8];
    const int bx = blockIdx.x;
    const int t = threadIdx.x;

    if (bx >= 1920) {
        const int wb = bx - 1920;
        const int branch = wb / 2304;
        const int win = wb - branch * 2304;
        const int Hw = win / 48, Ww = win % 48;
        if (t < 8) s_sc[t] = expf(fminf(ls[t], LOG_MAX));

        const int n = t / 25, tok = t % 25;
        const int wy = tok / 5, wx = tok % 5;
        const int py = Hw * 5 + wy, px = Ww * 5 + wx;
        int gy = py, gx = px;
        if (branch) { gy = (gy + 3) % IMGW; gx = (gx + 3) % IMGW; }
        const int pos = gy * IMGW + gx;

        if (t < 200) {
            const float* xb = g_conv1 + branch * 64 * HW;
            float4 kk, vv;
            kk.x = xb[(n * 4 + 0) * HW + pos];
            kk.y = xb[(n * 4 + 1) * HW + pos];
            kk.z = xb[(n * 4 + 2) * HW + pos];
            kk.w = xb[(n * 4 + 3) * HW + pos];
            vv.x = xb[(32 + n * 4 + 0) * HW + pos];
            vv.y = xb[(32 + n * 4 + 1) * HW + pos];
            vv.z = xb[(32 + n * 4 + 2) * HW + pos];
            vv.w = xb[(32 + n * 4 + 3) * HW + pos];
            kk = l2n(kk);
            s_k2[n * 25 + tok] = make_ulonglong2(pk2(kk.x, kk.y), pk2(kk.z, kk.w));
            s_v2[n * 25 + tok] = make_ulonglong2(pk2(vv.x, vv.y), pk2(vv.z, vv.w));
        }
        __syncthreads();
        if (t >= 200) return;

        const float* fb = g_conv1 + (192 + branch * 32) * HW;
        float4 q;
        q.x = fb[(n * 4 + 0) * HW + pos];
        q.y = fb[(n * 4 + 1) * HW + pos];
        q.z = fb[(n * 4 + 2) * HW + pos];
        q.w = fb[(n * 4 + 3) * HW + pos];
        q = l2n(q);
        const float sc = s_sc[n];
        const unsigned long long qxy = pk2(q.x * sc, q.y * sc);
        const unsigned long long qzw = pk2(q.z * sc, q.w * sc);

        float l = 0.f;
        unsigned long long axy = 0ull, azw = 0ull;
#pragma unroll
        for (int j = 0; j < 25; j++) {
            ulonglong2 kj = s_k2[n * 25 + j];
            ulonglong2 vj = s_v2[n * 25 + j];
            float2 ss = upk2(fma2(qzw, kj.y, mul2(qxy, kj.x)));
            float wgt = __expf(ss.x + ss.y);
            unsigned long long ww = pk2(wgt, wgt);
            axy = fma2(ww, vj.x, axy);
            azw = fma2(ww, vj.y, azw);
            l += wgt;
        }
        float invl = 1.f / l;
        float2 a01 = upk2(axy), a23 = upk2(azw);

        int oy = py, ox = px;
        if (branch) { oy = (oy + 2) % IMGW; ox = (ox + 2) % IMGW; }
        const int ppos = (oy + 1) * PW + (ox + 1);
        const int pair0 = branch * 16 + 2 * n;
        store_y_pair(pair0,     ppos, a01.x * invl, a01.y * invl);
        store_y_pair(pair0 + 1, ppos, a23.x * invl, a23.y * invl);
        return;
    }

    // ---- axial row attention: 2 queries/thread ----
    const int n = bx / IMGW, h = bx % IMGW;
    if (t == 0) s_sc[0] = expf(fminf(lrls[n], LOG_MAX));

    if (t < 240) {
        const int pos = h * IMGW + t;
        float4 kk, vv;
        kk.x = g_conv1[(128 + n * 4 + 0) * HW + pos];
        kk.y = g_conv1[(128 + n * 4 + 1) * HW + pos];
        kk.z = g_conv1[(128 + n * 4 + 2) * HW + pos];
        kk.w = g_conv1[(128 + n * 4 + 3) * HW + pos];
        vv.x = g_conv1[(160 + n * 4 + 0) * HW + pos];
        vv.y = g_conv1[(160 + n * 4 + 1) * HW + pos];
        vv.z = g_conv1[(160 + n * 4 + 2) * HW + pos];
        vv.w = g_conv1[(160 + n * 4 + 3) * HW + pos];
        kk = l2n(kk);
        s_k2[t] = make_ulonglong2(pk2(kk.x, kk.y), pk2(kk.z, kk.w));
        s_v2[t] = make_ulonglong2(pk2(vv.x, vv.y), pk2(vv.z, vv.w));
    }
    __syncthreads();
    if (t >= 120) return;

    const float sc = s_sc[0];
    const int posA = h * IMGW + t, posB = posA + 120;
    unsigned long long qxyA, qzwA, qxyB, qzwB;
    load_q(n, posA, sc, qxyA, qzwA);
    load_q(n, posB, sc, qxyB, qzwB);

    float lA = 0.f, lB = 0.f;
    unsigned long long axyA = 0ull, azwA = 0ull, axyB = 0ull, azwB = 0ull;
#pragma unroll 2
    for (int j = 0; j < 240; j++) {
        ulonglong2 kj = s_k2[j];
        ulonglong2 vj = s_v2[j];
        float2 sA = upk2(fma2(qzwA, kj.y, mul2(qxyA, kj.x)));
        float2 sB = upk2(fma2(qzwB, kj.y, mul2(qxyB, kj.x)));
        float wA = __expf(sA.x + sA.y);
        float wB = __expf(sB.x + sB.y);
        unsigned long long wwA = pk2(wA, wA);
        unsigned long long wwB = pk2(wB, wB);
        axyA = fma2(wwA, vj.x, axyA);
        azwA = fma2(wwA, vj.y, azwA);
        axyB = fma2(wwB, vj.x, axyB);
        azwB = fma2(wwB, vj.y, azwB);
        lA += wA;
        lB += wB;
    }
    float iA = 1.f / lA, iB = 1.f / lB;
    float2 a01A = upk2(axyA), a23A = upk2(azwA);
    float2 a01B = upk2(axyB), a23B = upk2(azwB);
    g_v1[(n * 4 + 0) * HW + posA] = a01A.x * iA;
    g_v1[(n * 4 + 1) * HW + posA] = a01A.y * iA;
    g_v1[(n * 4 + 2) * HW + posA] = a23A.x * iA;
    g_v1[(n * 4 + 3) * HW + posA] = a23A.y * iA;
    g_v1[(n * 4 + 0) * HW + posB] = a01B.x * iB;
    g_v1[(n * 4 + 1) * HW + posB] = a01B.y * iB;
    g_v1[(n * 4 + 2) * HW + posB] = a23B.x * iB;
    g_v1[(n * 4 + 3) * HW + posB] = a23B.y * iB;
}

// ---------------------------------------------------------------------------
// Axial column attention (unchanged from R10).
// ---------------------------------------------------------------------------
__global__ __launch_bounds__(128) void axial_col_kernel(const float* __restrict__ lrls) {
    const int n = blockIdx.x / IMGW, w = blockIdx.x % IMGW;
    const int t = threadIdx.x;
    __shared__ ulonglong2 s_k2[240];
    __shared__ ulonglong2 s_v2[240];
    __shared__ float s_sc;
    if (t == 0) s_sc = expf(fminf(lrls[n], LOG_MAX));

    for (int i = t; i < 240; i += 128) {
        const int pos = i * IMGW + w;
        float4 kk, vv;
        kk.x = g_conv1[(128 + n * 4 + 0) * HW + pos];
        kk.y = g_conv1[(128 + n * 4 + 1) * HW + pos];
        kk.z = g_conv1[(128 + n * 4 + 2) * HW + pos];
        kk.w = g_conv1[(128 + n * 4 + 3) * HW + pos];
        vv.x = g_v1[(n * 4 + 0) * HW + pos];
        vv.y = g_v1[(n * 4 + 1) * HW + pos];
        vv.z = g_v1[(n * 4 + 2) * HW + pos];
        vv.w = g_v1[(n * 4 + 3) * HW + pos];
        kk = l2n(kk);
        s_k2[i] = make_ulonglong2(pk2(kk.x, kk.y), pk2(kk.z, kk.w));
        s_v2[i] = make_ulonglong2(pk2(vv.x, vv.y), pk2(vv.z, vv.w));
    }
    __syncthreads();
    if (t >= 120) return;

    const float sc = s_sc;
    const int posA = t * IMGW + w, posB = (t + 120) * IMGW + w;
    unsigned long long qxyA, qzwA, qxyB, qzwB;
    load_q(n, posA, sc, qxyA, qzwA);
    load_q(n, posB, sc, qxyB, qzwB);

    float lA = 0.f, lB = 0.f;
    unsigned long long axyA = 0ull, azwA = 0ull, axyB = 0ull, azwB = 0ull;
#pragma unroll 2
    for (int j = 0; j < 240; j++) {
        ulonglong2 kj = s_k2[j];
        ulonglong2 vj = s_v2[j];
        float2 sA = upk2(fma2(qzwA, kj.y, mul2(qxyA, kj.x)));
        float2 sB = upk2(fma2(qzwB, kj.y, mul2(qxyB, kj.x)));
        float wA = __expf(sA.x + sA.y);
        float wB = __expf(sB.x + sB.y);
        unsigned long long wwA = pk2(wA, wA);
        unsigned long long wwB = pk2(wB, wB);
        axyA = fma2(wwA, vj.x, axyA);
        azwA = fma2(wwA, vj.y, azwA);
        axyB = fma2(wwB, vj.x, axyB);
        azwB = fma2(wwB, vj.y, azwB);
        lA += wA;
        lB += wB;
    }
    float iA = 1.f / lA, iB = 1.f / lB;
    float2 a01A = upk2(axyA), a23A = upk2(azwA);
    float2 a01B = upk2(axyB), a23B = upk2(azwB);
    const int pair0 = 32 + 2 * n;
    const int pposA = (t + 1) * PW + (w + 1);
    const int pposB = (t + 121) * PW + (w + 1);
    store_y_pair(pair0,     pposA, a01A.x * iA, a01A.y * iA);
    store_y_pair(pair0 + 1, pposA, a23A.x * iA, a23A.y * iA);
    store_y_pair(pair0,     pposB, a01B.x * iB, a01B.y * iB);
    store_y_pair(pair0 + 1, pposB, a23B.x * iB, a23B.y * iB);
}

// ---------------------------------------------------------------------------
extern "C" void kernel_launch(void* const* d_in, const int* in_sizes, int n_in,
                              void* d_out, int out_size) {
    const float* x      = (const float*)d_in[0];
    const float* w_in   = (const float*)d_in[1];
    const float* b_in   = (const float*)d_in[2];
    const float* w_f    = (const float*)d_in[3];
    const float* b_f    = (const float*)d_in[4];
    const float* w_out  = (const float*)d_in[5];
    const float* b_out  = (const float*)d_in[6];
    const float* ls     = (const float*)d_in[7];
    const float* lr_ls  = (const float*)d_in[8];
    float* out = (float*)d_out;

    float* p_conv1; unsigned* p_wrep; float* p_bias;
    unsigned *p_xh, *p_xl, *p_yh, *p_yl;
    cudaGetSymbolAddress((void**)&p_conv1, g_conv1);
    cudaGetSymbolAddress((void**)&p_wrep, g_wrep);
    cudaGetSymbolAddress((void**)&p_bias, g_bias);
    cudaGetSymbolAddress((void**)&p_xh, g_xa_hi);
    cudaGetSymbolAddress((void**)&p_xl, g_xa_lo);
    cudaGetSymbolAddress((void**)&p_yh, g_ya_hi);
    cudaGetSymbolAddress((void**)&p_yl, g_ya_lo);

    const int NTOT = NPREP_X + NPREP_B + 288 + NREPACK;
    prep_repack_kernel<<<(NTOT + 255) / 256, 256>>>(x, b_in, b_f, w_in, w_f, w_out);

    conv3x3_mma_kernel<<<dim3(15, 30, 3), 256>>>(p_xh, p_xl, p_wrep,
                                                 p_bias, p_conv1, 288);

    attn_winrow_kernel<<<1920 + 4608, 256>>>(ls, lr_ls);
    axial_col_kernel<<<8 * IMGW, 128>>>(lr_ls);

    unsigned* wrep_out = p_wrep + 2 * 288 * 432;
    conv3x3_mma_kernel<<<dim3(15, 30, 1), 256>>>(p_yh, p_yl, wrep_out,
                                                 b_out, out, 96);
}

// round 12
// speedup vs baseline: 1.2301x; 1.2301x over previous
#include <cuda_runtime.h>
#include <cuda_bf16.h>
#include <math.h>

#define HW    57600
#define IMGW  240
#define PW    244
#define PH    242
#define PHW   (PH * PW)      // 59048
#define LOG_MAX 4.6051701859880914f

// Scratch (allocation-free):
__device__ float    g_conv1[288 * HW];
__device__ float    g_v1[32 * HW];
__device__ unsigned g_wrep[768 * 864];
__device__ float    g_bias[288];
__device__ unsigned g_xa_hi[48 * PHW];
__device__ unsigned g_xa_lo[48 * PHW];
__device__ unsigned g_ya_hi[48 * PHW];
__device__ unsigned g_ya_lo[48 * PHW];

__device__ __forceinline__ unsigned pack_bf2(float a, float b) {
    __nv_bfloat162 h;
    h.x = __float2bfloat16_rn(a);
    h.y = __float2bfloat16_rn(b);
    return *(unsigned*)&h;
}
__device__ __forceinline__ unsigned smem_u32(const void* p) {
    return (unsigned)__cvta_generic_to_shared(p);
}
#define CP16(dst, src) asm volatile("cp.async.cg.shared.global [%0], [%1], 16;" :: "r"(dst), "l"(src))
#define CP8(dst, src)  asm volatile("cp.async.ca.shared.global [%0], [%1], 8;"  :: "r"(dst), "l"(src))
#define CP_COMMIT()    asm volatile("cp.async.commit_group;" ::: "memory")
#define CP_WAIT2()     asm volatile("cp.async.wait_group 2;" ::: "memory")

// ---- packed f32x2 helpers ----
__device__ __forceinline__ unsigned long long mul2(unsigned long long a,
                                                   unsigned long long b) {
    unsigned long long d;
    asm("mul.rn.f32x2 %0, %1, %2;" : "=l"(d) : "l"(a), "l"(b));
    return d;
}
__device__ __forceinline__ unsigned long long fma2(unsigned long long a,
                                                   unsigned long long b,
                                                   unsigned long long c) {
    unsigned long long d;
    asm("fma.rn.f32x2 %0, %1, %2, %3;" : "=l"(d) : "l"(a), "l"(b), "l"(c));
    return d;
}
__device__ __forceinline__ unsigned long long pk2(float lo, float hi) {
    unsigned long long r;
    asm("mov.b64 %0, {%1,%2};" : "=l"(r) : "f"(lo), "f"(hi));
    return r;
}
__device__ __forceinline__ float2 upk2(unsigned long long v) {
    float2 f;
    asm("mov.b64 {%0,%1}, %2;" : "=f"(f.x), "=f"(f.y) : "l"(v));
    return f;
}

// ---------------------------------------------------------------------------
// Fused prep + weight repack in ONE launch.
// ---------------------------------------------------------------------------
#define NPREP_X (48 * PHW)
#define NPREP_B (48 * (2 * PW + 4 * 240))
#define NREPACK (384 * 432)

__device__ __forceinline__ void repack_one(const float* wt, unsigned* wrep,
                                           int idx, int CoutLocal, int ocOff,
                                           int CoutTotal) {
    int o = idx % CoutLocal;
    int rem = idx / CoutLocal;
    int p = rem % 8; int rem2 = rem / 8;
    int s = rem2 % 9;
    int ch = rem2 / 9;
    int ic = ch * 16 + 2 * p;
    float v0 = wt[(o * 96 + ic) * 9 + s];
    float v1 = wt[(o * 96 + ic + 1) * 9 + s];
    __nv_bfloat16 h0 = __float2bfloat16_rn(v0);
    __nv_bfloat16 h1 = __float2bfloat16_rn(v1);
    __nv_bfloat162 hi; hi.x = h0; hi.y = h1;
    int dst = rem * CoutTotal + ocOff + o;
    wrep[dst] = *(unsigned*)&hi;
    wrep[CoutTotal * 432 + dst] =
        pack_bf2(v0 - __bfloat162float(h0), v1 - __bfloat162float(h1));
}

__global__ void prep_repack_kernel(const float* __restrict__ x,
                                   const float* __restrict__ b_in,
                                   const float* __restrict__ b_f,
                                   const float* __restrict__ w_in,
                                   const float* __restrict__ w_f,
                                   const float* __restrict__ w_out) {
    int idx = blockIdx.x * 256 + threadIdx.x;
    if (idx < NPREP_X) {
        int p = idx / PHW, rem = idx % PHW;
        int py = rem / PW, px = rem % PW;
        float v0 = 0.f, v1 = 0.f;
        if (py >= 1 && py <= 240 && px >= 1 && px <= 240) {
            int pos = (py - 1) * IMGW + (px - 1);
            v0 = x[(2 * p) * HW + pos];
            v1 = x[(2 * p + 1) * HW + pos];
        }
        __nv_bfloat16 h0 = __float2bfloat16_rn(v0);
        __nv_bfloat16 h1 = __float2bfloat16_rn(v1);
        __nv_bfloat162 hh; hh.x = h0; hh.y = h1;
        g_xa_hi[idx] = *(unsigned*)&hh;
        g_xa_lo[idx] = pack_bf2(v0 - __bfloat162float(h0), v1 - __bfloat162float(h1));
        return;
    }
    idx -= NPREP_X;
    if (idx < NPREP_B) {
        const int PER = 2 * PW + 4 * 240;
        int p = idx / PER, j = idx % PER;
        int py, px;
        if (j < 2 * PW) { py = (j / PW) ? 241 : 0; px = j % PW; }
        else {
            int k = j - 2 * PW;
            py = 1 + (k % 240);
            int c = k / 240;
            px = (c == 0) ? 0 : 240 + c;
        }
        int o = p * PHW + py * PW + px;
        g_ya_hi[o] = 0u;
        g_ya_lo[o] = 0u;
        return;
    }
    idx -= NPREP_B;
    if (idx < 288) {
        g_bias[idx] = idx < 192 ? b_in[idx] : b_f[idx - 192];
        return;
    }
    idx -= 288;
    const int T1 = 192 * 432, T2 = 96 * 432;
    if (idx < T1) { repack_one(w_in, g_wrep, idx, 192, 0, 288); return; }
    idx -= T1;
    if (idx < T2) { repack_one(w_f, g_wrep, idx, 96, 192, 288); return; }
    idx -= T2;
    if (idx < T2) repack_one(w_out, g_wrep + 2 * 288 * 432, idx, 96, 0, 96);
}

// ---------------------------------------------------------------------------
// Implicit-GEMM 3x3 conv, m16n8k16 bf16, 2-way split. (REVERTED to R8/R10
// best-known: cp.async-staged B in shift-halves, A double-buffered.)
// ---------------------------------------------------------------------------
__global__ __launch_bounds__(256, 2) void conv3x3_mma_kernel(
    const unsigned* __restrict__ in_hi, const unsigned* __restrict__ in_lo,
    const unsigned* __restrict__ wrep, const float* __restrict__ bias,
    float* __restrict__ out, int Cout) {
    extern __shared__ unsigned smem[];
    unsigned* s_b_hi = smem + 6400;
    unsigned* s_b_lo = smem + 13312;

    const int tid = threadIdx.x;
    const int lane = tid & 31, w = tid >> 5;
    const int wm = w & 1, wn = w >> 1;
    const int x0 = blockIdx.x * 16, y0 = blockIdx.y * 8;
    const int oc_blk = blockIdx.z * 96;
    const int g = lane >> 2, t = lane & 3;
    const int wlo = Cout * 432;

    auto stage_a = [&](int ch, int buf) {
        unsigned* a_base = smem + buf * 3200;
        for (int i = tid; i < 800; i += 256) {
            int p = i / 100, r = i % 100;
            int ly = r / 10, seg = r % 10;
            int is_lo = seg >= 5, s5 = seg - is_lo * 5;
            int lx = s5 * 4;
            const unsigned* src = (is_lo ? in_lo : in_hi) +
                                  (ch * 8 + p) * PHW + (y0 + ly) * PW + x0 + lx;
            unsigned dst = smem_u32(a_base + is_lo * 1600 + p * 200 + ly * 20 + lx);
            if (s5 < 4) CP16(dst, src);
            else        CP8(dst, src);
        }
    };
    auto stage_b_rows = [&](int ch, int r0, int nrows) {
        int half = nrows * 24;
        for (int i = tid; i < half * 2; i += 256) {
            int is_lo = i >= half, k = i - is_lo * half;
            int r = r0 + k / 24, c = k % 24;
            const unsigned* src = wrep + is_lo * wlo +
                                  (ch * 72 + r) * Cout + oc_blk + c * 4;
            int col = (c * 4) ^ ((r & 3) * 8);
            unsigned dst = smem_u32((is_lo ? s_b_lo : s_b_hi) + r * 96 + col);
            CP16(dst, src);
        }
    };

    float acc[4][3][4];
#pragma unroll
    for (int j = 0; j < 3; j++) {
        int oc = oc_blk + wn * 24 + j * 8 + 2 * t;
        float b0 = bias[oc], b1 = bias[oc + 1];
#pragma unroll
        for (int i = 0; i < 4; i++) {
            acc[i][j][0] = b0; acc[i][j][1] = b1;
            acc[i][j][2] = b0; acc[i][j][3] = b1;
        }
    }

    stage_a(0, 0);           CP_COMMIT();
    stage_b_rows(0, 0, 40);  CP_COMMIT();
    stage_b_rows(0, 40, 32); CP_COMMIT();

    const unsigned* a_hi;
    const unsigned* a_lo;
    auto compute_shift = [&](int s) {
        const int dy = s / 3, dx = s % 3;
        unsigned bh[3][2], bl[3][2];
        const int swz = t * 8;
#pragma unroll
        for (int j = 0; j < 3; j++) {
            int oc = (wn * 24 + j * 8 + g) ^ swz;
            bh[j][0] = s_b_hi[(s * 8 + t) * 96 + oc];
            bh[j][1] = s_b_hi[(s * 8 + t + 4) * 96 + oc];
            bl[j][0] = s_b_lo[(s * 8 + t) * 96 + oc];
            bl[j][1] = s_b_lo[(s * 8 + t + 4) * 96 + oc];
        }
#pragma unroll
        for (int i = 0; i < 4; i++) {
            int py = wm * 4 + i;
            int o00 = t * 200 + (py + dy) * 20 + g + dx;
            int o4  = o00 + 800;
            unsigned ah0 = a_hi[o00], ah1 = a_hi[o00 + 8];
            unsigned ah2 = a_hi[o4],  ah3 = a_hi[o4 + 8];
            unsigned al0 = a_lo[o00], al1 = a_lo[o00 + 8];
            unsigned al2 = a_lo[o4],  al3 = a_lo[o4 + 8];
#pragma unroll
            for (int j = 0; j < 3; j++) {
                asm volatile(
                    "mma.sync.aligned.m16n8k16.row.col.f32.bf16.bf16.f32 "
                    "{%0,%1,%2,%3}, {%4,%5,%6,%7}, {%8,%9}, {%0,%1,%2,%3};"
                    : "+f"(acc[i][j][0]), "+f"(acc[i][j][1]),
                      "+f"(acc[i][j][2]), "+f"(acc[i][j][3])
                    : "r"(al0), "r"(al1), "r"(al2), "r"(al3),
                      "r"(bh[j][0]), "r"(bh[j][1]));
                asm volatile(
                    "mma.sync.aligned.m16n8k16.row.col.f32.bf16.bf16.f32 "
                    "{%0,%1,%2,%3}, {%4,%5,%6,%7}, {%8,%9}, {%0,%1,%2,%3};"
                    : "+f"(acc[i][j][0]), "+f"(acc[i][j][1]),
                      "+f"(acc[i][j][2]), "+f"(acc[i][j][3])
                    : "r"(ah0), "r"(ah1), "r"(ah2), "r"(ah3),
                      "r"(bl[j][0]), "r"(bl[j][1]));
                asm volatile(
                    "mma.sync.aligned.m16n8k16.row.col.f32.bf16.bf16.f32 "
                    "{%0,%1,%2,%3}, {%4,%5,%6,%7}, {%8,%9}, {%0,%1,%2,%3};"
                    : "+f"(acc[i][j][0]), "+f"(acc[i][j][1]),
                      "+f"(acc[i][j][2]), "+f"(acc[i][j][3])
                    : "r"(ah0), "r"(ah1), "r"(ah2), "r"(ah3),
                      "r"(bh[j][0]), "r"(bh[j][1]));
            }
        }
    };

    for (int ch = 0; ch < 6; ch++) {
        if (ch < 5) stage_a(ch + 1, (ch + 1) & 1);
        CP_COMMIT();
        CP_WAIT2();
        __syncthreads();

        a_hi = smem + (ch & 1) * 3200;
        a_lo = a_hi + 1600;
#pragma unroll
        for (int s = 0; s < 5; s++) compute_shift(s);
        __syncthreads();

        if (ch < 5) stage_b_rows(ch + 1, 0, 40);
        CP_COMMIT();
        CP_WAIT2();
        __syncthreads();
#pragma unroll
        for (int s = 5; s < 9; s++) compute_shift(s);
        __syncthreads();

        if (ch < 5) stage_b_rows(ch + 1, 40, 32);
        CP_COMMIT();
    }

    const int gx0 = x0 + g;
#pragma unroll
    for (int i = 0; i < 4; i++) {
        int gy = y0 + wm * 4 + i;
#pragma unroll
        for (int j = 0; j < 3; j++) {
            int oc = oc_blk + wn * 24 + j * 8 + 2 * t;
            out[oc * HW + gy * IMGW + gx0] = acc[i][j][0];
            out[(oc + 1) * HW + gy * IMGW + gx0] = acc[i][j][1];
            out[oc * HW + gy * IMGW + gx0 + 8] = acc[i][j][2];
            out[(oc + 1) * HW + gy * IMGW + gx0 + 8] = acc[i][j][3];
        }
    }
}

__device__ __forceinline__ float4 l2n(float4 a) {
    float n = sqrtf(a.x * a.x + a.y * a.y + a.z * a.z + a.w * a.w);
    float inv = 1.f / fmaxf(n, 1e-12f);
    a.x *= inv; a.y *= inv; a.z *= inv; a.w *= inv;
    return a;
}

__device__ __forceinline__ void store_y_pair(int pair, int ppos, float a, float b) {
    __nv_bfloat16 ha = __float2bfloat16_rn(a), hb = __float2bfloat16_rn(b);
    __nv_bfloat162 hh; hh.x = ha; hh.y = hb;
    g_ya_hi[pair * PHW + ppos] = *(unsigned*)&hh;
    g_ya_lo[pair * PHW + ppos] =
        pack_bf2(a - __bfloat162float(ha), b - __bfloat162float(hb));
}

__device__ __forceinline__ void load_q(int n, int pos, float sc,
                                       unsigned long long& qxy,
                                       unsigned long long& qzw) {
    float4 q;
    q.x = g_conv1[(256 + n * 4 + 0) * HW + pos];
    q.y = g_conv1[(256 + n * 4 + 1) * HW + pos];
    q.z = g_conv1[(256 + n * 4 + 2) * HW + pos];
    q.w = g_conv1[(256 + n * 4 + 3) * HW + pos];
    q = l2n(q);
    qxy = pk2(q.x * sc, q.y * sc);
    qzw = pk2(q.z * sc, q.w * sc);
}

// ---------------------------------------------------------------------------
// Attention launch #1: axial ROW only (1920 blocks; 2 queries/thread).
// ---------------------------------------------------------------------------
__global__ __launch_bounds__(256) void axial_row_kernel(const float* __restrict__ lrls) {
    __shared__ ulonglong2 s_k2[240];
    __shared__ ulonglong2 s_v2[240];
    __shared__ float s_sc;
    const int n = blockIdx.x / IMGW, h = blockIdx.x % IMGW;
    const int t = threadIdx.x;
    if (t == 0) s_sc = expf(fminf(lrls[n], LOG_MAX));

    if (t < 240) {
        const int pos = h * IMGW + t;
        float4 kk, vv;
        kk.x = g_conv1[(128 + n * 4 + 0) * HW + pos];
        kk.y = g_conv1[(128 + n * 4 + 1) * HW + pos];
        kk.z = g_conv1[(128 + n * 4 + 2) * HW + pos];
        kk.w = g_conv1[(128 + n * 4 + 3) * HW + pos];
        vv.x = g_conv1[(160 + n * 4 + 0) * HW + pos];
        vv.y = g_conv1[(160 + n * 4 + 1) * HW + pos];
        vv.z = g_conv1[(160 + n * 4 + 2) * HW + pos];
        vv.w = g_conv1[(160 + n * 4 + 3) * HW + pos];
        kk = l2n(kk);
        s_k2[t] = make_ulonglong2(pk2(kk.x, kk.y), pk2(kk.z, kk.w));
        s_v2[t] = make_ulonglong2(pk2(vv.x, vv.y), pk2(vv.z, vv.w));
    }
    __syncthreads();
    if (t >= 120) return;

    const float sc = s_sc;
    const int posA = h * IMGW + t, posB = posA + 120;
    unsigned long long qxyA, qzwA, qxyB, qzwB;
    load_q(n, posA, sc, qxyA, qzwA);
    load_q(n, posB, sc, qxyB, qzwB);

    float lA = 0.f, lB = 0.f;
    unsigned long long axyA = 0ull, azwA = 0ull, axyB = 0ull, azwB = 0ull;
#pragma unroll 2
    for (int j = 0; j < 240; j++) {
        ulonglong2 kj = s_k2[j];
        ulonglong2 vj = s_v2[j];
        float2 sA = upk2(fma2(qzwA, kj.y, mul2(qxyA, kj.x)));
        float2 sB = upk2(fma2(qzwB, kj.y, mul2(qxyB, kj.x)));
        float wA = __expf(sA.x + sA.y);
        float wB = __expf(sB.x + sB.y);
        unsigned long long wwA = pk2(wA, wA);
        unsigned long long wwB = pk2(wB, wB);
        axyA = fma2(wwA, vj.x, axyA);
        azwA = fma2(wwA, vj.y, azwA);
        axyB = fma2(wwB, vj.x, axyB);
        azwB = fma2(wwB, vj.y, azwB);
        lA += wA;
        lB += wB;
    }
    float iA = 1.f / lA, iB = 1.f / lB;
    float2 a01A = upk2(axyA), a23A = upk2(azwA);
    float2 a01B = upk2(axyB), a23B = upk2(azwB);
    g_v1[(n * 4 + 0) * HW + posA] = a01A.x * iA;
    g_v1[(n * 4 + 1) * HW + posA] = a01A.y * iA;
    g_v1[(n * 4 + 2) * HW + posA] = a23A.x * iA;
    g_v1[(n * 4 + 3) * HW + posA] = a23A.y * iA;
    g_v1[(n * 4 + 0) * HW + posB] = a01B.x * iB;
    g_v1[(n * 4 + 1) * HW + posB] = a01B.y * iB;
    g_v1[(n * 4 + 2) * HW + posB] = a23B.x * iB;
    g_v1[(n * 4 + 3) * HW + posB] = a23B.y * iB;
}

// ---------------------------------------------------------------------------
// Attention launch #2: heavy axial COL blocks (bx<1920, 2 q/thread) first,
// then light WINDOW blocks fill the tail (independent of row/col).
// ---------------------------------------------------------------------------
__global__ __launch_bounds__(256) void attn_wincol_kernel(
    const float* __restrict__ ls, const float* __restrict__ lrls) {
    __shared__ ulonglong2 s_k2[240];
    __shared__ ulonglong2 s_v2[240];
    __shared__ float s_sc[8];
    const int bx = blockIdx.x;
    const int t = threadIdx.x;

    if (bx >= 1920) {
        // ---- window attention ----
        const int wb = bx - 1920;
        const int branch = wb / 2304;
        const int win = wb - branch * 2304;
        const int Hw = win / 48, Ww = win % 48;
        if (t < 8) s_sc[t] = expf(fminf(ls[t], LOG_MAX));

        const int n = t / 25, tok = t % 25;
        const int wy = tok / 5, wx = tok % 5;
        const int py = Hw * 5 + wy, px = Ww * 5 + wx;
        int gy = py, gx = px;
        if (branch) { gy = (gy + 3) % IMGW; gx = (gx + 3) % IMGW; }
        const int pos = gy * IMGW + gx;

        if (t < 200) {
            const float* xb = g_conv1 + branch * 64 * HW;
            float4 kk, vv;
            kk.x = xb[(n * 4 + 0) * HW + pos];
            kk.y = xb[(n * 4 + 1) * HW + pos];
            kk.z = xb[(n * 4 + 2) * HW + pos];
            kk.w = xb[(n * 4 + 3) * HW + pos];
            vv.x = xb[(32 + n * 4 + 0) * HW + pos];
            vv.y = xb[(32 + n * 4 + 1) * HW + pos];
            vv.z = xb[(32 + n * 4 + 2) * HW + pos];
            vv.w = xb[(32 + n * 4 + 3) * HW + pos];
            kk = l2n(kk);
            s_k2[n * 25 + tok] = make_ulonglong2(pk2(kk.x, kk.y), pk2(kk.z, kk.w));
            s_v2[n * 25 + tok] = make_ulonglong2(pk2(vv.x, vv.y), pk2(vv.z, vv.w));
        }
        __syncthreads();
        if (t >= 200) return;

        const float* fb = g_conv1 + (192 + branch * 32) * HW;
        float4 q;
        q.x = fb[(n * 4 + 0) * HW + pos];
        q.y = fb[(n * 4 + 1) * HW + pos];
        q.z = fb[(n * 4 + 2) * HW + pos];
        q.w = fb[(n * 4 + 3) * HW + pos];
        q = l2n(q);
        const float sc = s_sc[n];
        const unsigned long long qxy = pk2(q.x * sc, q.y * sc);
        const unsigned long long qzw = pk2(q.z * sc, q.w * sc);

        float l = 0.f;
        unsigned long long axy = 0ull, azw = 0ull;
#pragma unroll
        for (int j = 0; j < 25; j++) {
            ulonglong2 kj = s_k2[n * 25 + j];
            ulonglong2 vj = s_v2[n * 25 + j];
            float2 ss = upk2(fma2(qzw, kj.y, mul2(qxy, kj.x)));
            float wgt = __expf(ss.x + ss.y);
            unsigned long long ww = pk2(wgt, wgt);
            axy = fma2(ww, vj.x, axy);
            azw = fma2(ww, vj.y, azw);
            l += wgt;
        }
        float invl = 1.f / l;
        float2 a01 = upk2(axy), a23 = upk2(azw);

        int oy = py, ox = px;
        if (branch) { oy = (oy + 2) % IMGW; ox = (ox + 2) % IMGW; }
        const int ppos = (oy + 1) * PW + (ox + 1);
        const int pair0 = branch * 16 + 2 * n;
        store_y_pair(pair0,     ppos, a01.x * invl, a01.y * invl);
        store_y_pair(pair0 + 1, ppos, a23.x * invl, a23.y * invl);
        return;
    }

    // ---- axial column attention (heavy; scheduled first) ----
    const int n = bx / IMGW, w = bx % IMGW;
    if (t == 0) s_sc[0] = expf(fminf(lrls[n], LOG_MAX));

    if (t < 240) {
        const int pos = t * IMGW + w;
        float4 kk, vv;
        kk.x = g_conv1[(128 + n * 4 + 0) * HW + pos];
        kk.y = g_conv1[(128 + n * 4 + 1) * HW + pos];
        kk.z = g_conv1[(128 + n * 4 + 2) * HW + pos];
        kk.w = g_conv1[(128 + n * 4 + 3) * HW + pos];
        vv.x = g_v1[(n * 4 + 0) * HW + pos];
        vv.y = g_v1[(n * 4 + 1) * HW + pos];
        vv.z = g_v1[(n * 4 + 2) * HW + pos];
        vv.w = g_v1[(n * 4 + 3) * HW + pos];
        kk = l2n(kk);
        s_k2[t] = make_ulonglong2(pk2(kk.x, kk.y), pk2(kk.z, kk.w));
        s_v2[t] = make_ulonglong2(pk2(vv.x, vv.y), pk2(vv.z, vv.w));
    }
    __syncthreads();
    if (t >= 120) return;

    const float sc = s_sc[0];
    const int posA = t * IMGW + w, posB = (t + 120) * IMGW + w;
    unsigned long long qxyA, qzwA, qxyB, qzwB;
    load_q(n, posA, sc, qxyA, qzwA);
    load_q(n, posB, sc, qxyB, qzwB);

    float lA = 0.f, lB = 0.f;
    unsigned long long axyA = 0ull, azwA = 0ull, axyB = 0ull, azwB = 0ull;
#pragma unroll 2
    for (int j = 0; j < 240; j++) {
        ulonglong2 kj = s_k2[j];
        ulonglong2 vj = s_v2[j];
        float2 sA = upk2(fma2(qzwA, kj.y, mul2(qxyA, kj.x)));
        float2 sB = upk2(fma2(qzwB, kj.y, mul2(qxyB, kj.x)));
        float wA = __expf(sA.x + sA.y);
        float wB = __expf(sB.x + sB.y);
        unsigned long long wwA = pk2(wA, wA);
        unsigned long long wwB = pk2(wB, wB);
        axyA = fma2(wwA, vj.x, axyA);
        azwA = fma2(wwA, vj.y, azwA);
        axyB = fma2(wwB, vj.x, axyB);
        azwB = fma2(wwB, vj.y, azwB);
        lA += wA;
        lB += wB;
    }
    float iA = 1.f / lA, iB = 1.f / lB;
    float2 a01A = upk2(axyA), a23A = upk2(azwA);
    float2 a01B = upk2(axyB), a23B = upk2(azwB);
    const int pair0 = 32 + 2 * n;
    const int pposA = (t + 1) * PW + (w + 1);
    const int pposB = (t + 121) * PW + (w + 1);
    store_y_pair(pair0,     pposA, a01A.x * iA, a01A.y * iA);
    store_y_pair(pair0 + 1, pposA, a23A.x * iA, a23A.y * iA);
    store_y_pair(pair0,     pposB, a01B.x * iB, a01B.y * iB);
    store_y_pair(pair0 + 1, pposB, a23B.x * iB, a23B.y * iB);
}

// ---------------------------------------------------------------------------
extern "C" void kernel_launch(void* const* d_in, const int* in_sizes, int n_in,
                              void* d_out, int out_size) {
    const float* x      = (const float*)d_in[0];
    const float* w_in   = (const float*)d_in[1];
    const float* b_in   = (const float*)d_in[2];
    const float* w_f    = (const float*)d_in[3];
    const float* b_f    = (const float*)d_in[4];
    const float* w_out  = (const float*)d_in[5];
    const float* b_out  = (const float*)d_in[6];
    const float* ls     = (const float*)d_in[7];
    const float* lr_ls  = (const float*)d_in[8];
    float* out = (float*)d_out;

    float* p_conv1; unsigned* p_wrep; float* p_bias;
    unsigned *p_xh, *p_xl, *p_yh, *p_yl;
    cudaGetSymbolAddress((void**)&p_conv1, g_conv1);
    cudaGetSymbolAddress((void**)&p_wrep, g_wrep);
    cudaGetSymbolAddress((void**)&p_bias, g_bias);
    cudaGetSymbolAddress((void**)&p_xh, g_xa_hi);
    cudaGetSymbolAddress((void**)&p_xl, g_xa_lo);
    cudaGetSymbolAddress((void**)&p_yh, g_ya_hi);
    cudaGetSymbolAddress((void**)&p_yl, g_ya_lo);

    const int SMEM_BYTES = 20224 * 4;
    static int attr_set = 0;
    if (!attr_set) {
        cudaFuncSetAttribute(conv3x3_mma_kernel,
                             cudaFuncAttributeMaxDynamicSharedMemorySize, SMEM_BYTES);
        attr_set = 1;
    }

    const int NTOT = NPREP_X + NPREP_B + 288 + NREPACK;
    prep_repack_kernel<<<(NTOT + 255) / 256, 256>>>(x, b_in, b_f, w_in, w_f, w_out);

    conv3x3_mma_kernel<<<dim3(15, 30, 3), 256, SMEM_BYTES>>>(p_xh, p_xl, p_wrep,
                                                             p_bias, p_conv1, 288);

    axial_row_kernel<<<1920, 256>>>(lr_ls);
    attn_wincol_kernel<<<1920 + 4608, 256>>>(ls, lr_ls);

    unsigned* wrep_out = p_wrep + 2 * 288 * 432;
    conv3x3_mma_kernel<<<dim3(15, 30, 1), 256, SMEM_BYTES>>>(p_yh, p_yl, wrep_out,
                                                             b_out, out, 96);
}

// round 13
// speedup vs baseline: 1.2456x; 1.0126x over previous
#include <cuda_runtime.h>
#include <cuda_bf16.h>
#include <math.h>

#define HW    57600
#define IMGW  240
#define PW    244
#define PH    242
#define PHW   (PH * PW)      // 59048
#define LOG_MAX 4.6051701859880914f

// Scratch (allocation-free):
__device__ float    g_conv1[288 * HW];     // NHWC: [pos][ch], stride 288
__device__ float    g_v1[32 * HW];         // NHWC: [pos][ch], stride 32
__device__ unsigned g_wrep[768 * 864];
__device__ float    g_bias[288];
__device__ unsigned g_xa_hi[48 * PHW];
__device__ unsigned g_xa_lo[48 * PHW];
__device__ unsigned g_ya_hi[48 * PHW];
__device__ unsigned g_ya_lo[48 * PHW];

__device__ __forceinline__ unsigned pack_bf2(float a, float b) {
    __nv_bfloat162 h;
    h.x = __float2bfloat16_rn(a);
    h.y = __float2bfloat16_rn(b);
    return *(unsigned*)&h;
}
__device__ __forceinline__ unsigned smem_u32(const void* p) {
    return (unsigned)__cvta_generic_to_shared(p);
}
#define CP16(dst, src) asm volatile("cp.async.cg.shared.global [%0], [%1], 16;" :: "r"(dst), "l"(src))
#define CP8(dst, src)  asm volatile("cp.async.ca.shared.global [%0], [%1], 8;"  :: "r"(dst), "l"(src))
#define CP_COMMIT()    asm volatile("cp.async.commit_group;" ::: "memory")
#define CP_WAIT2()     asm volatile("cp.async.wait_group 2;" ::: "memory")

// ---- packed f32x2 helpers ----
__device__ __forceinline__ unsigned long long mul2(unsigned long long a,
                                                   unsigned long long b) {
    unsigned long long d;
    asm("mul.rn.f32x2 %0, %1, %2;" : "=l"(d) : "l"(a), "l"(b));
    return d;
}
__device__ __forceinline__ unsigned long long fma2(unsigned long long a,
                                                   unsigned long long b,
                                                   unsigned long long c) {
    unsigned long long d;
    asm("fma.rn.f32x2 %0, %1, %2, %3;" : "=l"(d) : "l"(a), "l"(b), "l"(c));
    return d;
}
__device__ __forceinline__ unsigned long long pk2(float lo, float hi) {
    unsigned long long r;
    asm("mov.b64 %0, {%1,%2};" : "=l"(r) : "f"(lo), "f"(hi));
    return r;
}
__device__ __forceinline__ float2 upk2(unsigned long long v) {
    float2 f;
    asm("mov.b64 {%0,%1}, %2;" : "=f"(f.x), "=f"(f.y) : "l"(v));
    return f;
}

// ---------------------------------------------------------------------------
// Fused prep + weight repack in ONE launch.
// ---------------------------------------------------------------------------
#define NPREP_X (48 * PHW)
#define NPREP_B (48 * (2 * PW + 4 * 240))
#define NREPACK (384 * 432)

__device__ __forceinline__ void repack_one(const float* wt, unsigned* wrep,
                                           int idx, int CoutLocal, int ocOff,
                                           int CoutTotal) {
    int o = idx % CoutLocal;
    int rem = idx / CoutLocal;
    int p = rem % 8; int rem2 = rem / 8;
    int s = rem2 % 9;
    int ch = rem2 / 9;
    int ic = ch * 16 + 2 * p;
    float v0 = wt[(o * 96 + ic) * 9 + s];
    float v1 = wt[(o * 96 + ic + 1) * 9 + s];
    __nv_bfloat16 h0 = __float2bfloat16_rn(v0);
    __nv_bfloat16 h1 = __float2bfloat16_rn(v1);
    __nv_bfloat162 hi; hi.x = h0; hi.y = h1;
    int dst = rem * CoutTotal + ocOff + o;
    wrep[dst] = *(unsigned*)&hi;
    wrep[CoutTotal * 432 + dst] =
        pack_bf2(v0 - __bfloat162float(h0), v1 - __bfloat162float(h1));
}

__global__ void prep_repack_kernel(const float* __restrict__ x,
                                   const float* __restrict__ b_in,
                                   const float* __restrict__ b_f,
                                   const float* __restrict__ w_in,
                                   const float* __restrict__ w_f,
                                   const float* __restrict__ w_out) {
    int idx = blockIdx.x * 256 + threadIdx.x;
    if (idx < NPREP_X) {
        int p = idx / PHW, rem = idx % PHW;
        int py = rem / PW, px = rem % PW;
        float v0 = 0.f, v1 = 0.f;
        if (py >= 1 && py <= 240 && px >= 1 && px <= 240) {
            int pos = (py - 1) * IMGW + (px - 1);
            v0 = x[(2 * p) * HW + pos];
            v1 = x[(2 * p + 1) * HW + pos];
        }
        __nv_bfloat16 h0 = __float2bfloat16_rn(v0);
        __nv_bfloat16 h1 = __float2bfloat16_rn(v1);
        __nv_bfloat162 hh; hh.x = h0; hh.y = h1;
        g_xa_hi[idx] = *(unsigned*)&hh;
        g_xa_lo[idx] = pack_bf2(v0 - __bfloat162float(h0), v1 - __bfloat162float(h1));
        return;
    }
    idx -= NPREP_X;
    if (idx < NPREP_B) {
        const int PER = 2 * PW + 4 * 240;
        int p = idx / PER, j = idx % PER;
        int py, px;
        if (j < 2 * PW) { py = (j / PW) ? 241 : 0; px = j % PW; }
        else {
            int k = j - 2 * PW;
            py = 1 + (k % 240);
            int c = k / 240;
            px = (c == 0) ? 0 : 240 + c;
        }
        int o = p * PHW + py * PW + px;
        g_ya_hi[o] = 0u;
        g_ya_lo[o] = 0u;
        return;
    }
    idx -= NPREP_B;
    if (idx < 288) {
        g_bias[idx] = idx < 192 ? b_in[idx] : b_f[idx - 192];
        return;
    }
    idx -= 288;
    const int T1 = 192 * 432, T2 = 96 * 432;
    if (idx < T1) { repack_one(w_in, g_wrep, idx, 192, 0, 288); return; }
    idx -= T1;
    if (idx < T2) { repack_one(w_f, g_wrep, idx, 96, 192, 288); return; }
    idx -= T2;
    if (idx < T2) repack_one(w_out, g_wrep + 2 * 288 * 432, idx, 96, 0, 96);
}

// ---------------------------------------------------------------------------
// Implicit-GEMM 3x3 conv (R8 best-known pipeline). out_nhwc: 0 = planar
// (oc*HW+pos, for final output), 1 = NHWC pos*288+oc (for g_conv1).
// ---------------------------------------------------------------------------
__global__ __launch_bounds__(256, 2) void conv3x3_mma_kernel(
    const unsigned* __restrict__ in_hi, const unsigned* __restrict__ in_lo,
    const unsigned* __restrict__ wrep, const float* __restrict__ bias,
    float* __restrict__ out, int Cout, int out_nhwc) {
    extern __shared__ unsigned smem[];
    unsigned* s_b_hi = smem + 6400;
    unsigned* s_b_lo = smem + 13312;

    const int tid = threadIdx.x;
    const int lane = tid & 31, w = tid >> 5;
    const int wm = w & 1, wn = w >> 1;
    const int x0 = blockIdx.x * 16, y0 = blockIdx.y * 8;
    const int oc_blk = blockIdx.z * 96;
    const int g = lane >> 2, t = lane & 3;
    const int wlo = Cout * 432;

    auto stage_a = [&](int ch, int buf) {
        unsigned* a_base = smem + buf * 3200;
        for (int i = tid; i < 800; i += 256) {
            int p = i / 100, r = i % 100;
            int ly = r / 10, seg = r % 10;
            int is_lo = seg >= 5, s5 = seg - is_lo * 5;
            int lx = s5 * 4;
            const unsigned* src = (is_lo ? in_lo : in_hi) +
                                  (ch * 8 + p) * PHW + (y0 + ly) * PW + x0 + lx;
            unsigned dst = smem_u32(a_base + is_lo * 1600 + p * 200 + ly * 20 + lx);
            if (s5 < 4) CP16(dst, src);
            else        CP8(dst, src);
        }
    };
    auto stage_b_rows = [&](int ch, int r0, int nrows) {
        int half = nrows * 24;
        for (int i = tid; i < half * 2; i += 256) {
            int is_lo = i >= half, k = i - is_lo * half;
            int r = r0 + k / 24, c = k % 24;
            const unsigned* src = wrep + is_lo * wlo +
                                  (ch * 72 + r) * Cout + oc_blk + c * 4;
            int col = (c * 4) ^ ((r & 3) * 8);
            unsigned dst = smem_u32((is_lo ? s_b_lo : s_b_hi) + r * 96 + col);
            CP16(dst, src);
        }
    };

    float acc[4][3][4];
#pragma unroll
    for (int j = 0; j < 3; j++) {
        int oc = oc_blk + wn * 24 + j * 8 + 2 * t;
        float b0 = bias[oc], b1 = bias[oc + 1];
#pragma unroll
        for (int i = 0; i < 4; i++) {
            acc[i][j][0] = b0; acc[i][j][1] = b1;
            acc[i][j][2] = b0; acc[i][j][3] = b1;
        }
    }

    stage_a(0, 0);           CP_COMMIT();
    stage_b_rows(0, 0, 40);  CP_COMMIT();
    stage_b_rows(0, 40, 32); CP_COMMIT();

    const unsigned* a_hi;
    const unsigned* a_lo;
    auto compute_shift = [&](int s) {
        const int dy = s / 3, dx = s % 3;
        unsigned bh[3][2], bl[3][2];
        const int swz = t * 8;
#pragma unroll
        for (int j = 0; j < 3; j++) {
            int oc = (wn * 24 + j * 8 + g) ^ swz;
            bh[j][0] = s_b_hi[(s * 8 + t) * 96 + oc];
            bh[j][1] = s_b_hi[(s * 8 + t + 4) * 96 + oc];
            bl[j][0] = s_b_lo[(s * 8 + t) * 96 + oc];
            bl[j][1] = s_b_lo[(s * 8 + t + 4) * 96 + oc];
        }
#pragma unroll
        for (int i = 0; i < 4; i++) {
            int py = wm * 4 + i;
            int o00 = t * 200 + (py + dy) * 20 + g + dx;
            int o4  = o00 + 800;
            unsigned ah0 = a_hi[o00], ah1 = a_hi[o00 + 8];
            unsigned ah2 = a_hi[o4],  ah3 = a_hi[o4 + 8];
            unsigned al0 = a_lo[o00], al1 = a_lo[o00 + 8];
            unsigned al2 = a_lo[o4],  al3 = a_lo[o4 + 8];
#pragma unroll
            for (int j = 0; j < 3; j++) {
                asm volatile(
                    "mma.sync.aligned.m16n8k16.row.col.f32.bf16.bf16.f32 "
                    "{%0,%1,%2,%3}, {%4,%5,%6,%7}, {%8,%9}, {%0,%1,%2,%3};"
                    : "+f"(acc[i][j][0]), "+f"(acc[i][j][1]),
                      "+f"(acc[i][j][2]), "+f"(acc[i][j][3])
                    : "r"(al0), "r"(al1), "r"(al2), "r"(al3),
                      "r"(bh[j][0]), "r"(bh[j][1]));
                asm volatile(
                    "mma.sync.aligned.m16n8k16.row.col.f32.bf16.bf16.f32 "
                    "{%0,%1,%2,%3}, {%4,%5,%6,%7}, {%8,%9}, {%0,%1,%2,%3};"
                    : "+f"(acc[i][j][0]), "+f"(acc[i][j][1]),
                      "+f"(acc[i][j][2]), "+f"(acc[i][j][3])
                    : "r"(ah0), "r"(ah1), "r"(ah2), "r"(ah3),
                      "r"(bl[j][0]), "r"(bl[j][1]));
                asm volatile(
                    "mma.sync.aligned.m16n8k16.row.col.f32.bf16.bf16.f32 "
                    "{%0,%1,%2,%3}, {%4,%5,%6,%7}, {%8,%9}, {%0,%1,%2,%3};"
                    : "+f"(acc[i][j][0]), "+f"(acc[i][j][1]),
                      "+f"(acc[i][j][2]), "+f"(acc[i][j][3])
                    : "r"(ah0), "r"(ah1), "r"(ah2), "r"(ah3),
                      "r"(bh[j][0]), "r"(bh[j][1]));
            }
        }
    };

    for (int ch = 0; ch < 6; ch++) {
        if (ch < 5) stage_a(ch + 1, (ch + 1) & 1);
        CP_COMMIT();
        CP_WAIT2();
        __syncthreads();

        a_hi = smem + (ch & 1) * 3200;
        a_lo = a_hi + 1600;
#pragma unroll
        for (int s = 0; s < 5; s++) compute_shift(s);
        __syncthreads();

        if (ch < 5) stage_b_rows(ch + 1, 0, 40);
        CP_COMMIT();
        CP_WAIT2();
        __syncthreads();
#pragma unroll
        for (int s = 5; s < 9; s++) compute_shift(s);
        __syncthreads();

        if (ch < 5) stage_b_rows(ch + 1, 40, 32);
        CP_COMMIT();
    }

    const int gx0 = x0 + g;
    if (out_nhwc) {
#pragma unroll
        for (int i = 0; i < 4; i++) {
            int gy = y0 + wm * 4 + i;
            float* r0 = out + (gy * IMGW + gx0) * 288;
            float* r8 = r0 + 8 * 288;
#pragma unroll
            for (int j = 0; j < 3; j++) {
                int oc = oc_blk + wn * 24 + j * 8 + 2 * t;
                *(float2*)(r0 + oc) = make_float2(acc[i][j][0], acc[i][j][1]);
                *(float2*)(r8 + oc) = make_float2(acc[i][j][2], acc[i][j][3]);
            }
        }
    } else {
#pragma unroll
        for (int i = 0; i < 4; i++) {
            int gy = y0 + wm * 4 + i;
#pragma unroll
            for (int j = 0; j < 3; j++) {
                int oc = oc_blk + wn * 24 + j * 8 + 2 * t;
                out[oc * HW + gy * IMGW + gx0] = acc[i][j][0];
                out[(oc + 1) * HW + gy * IMGW + gx0] = acc[i][j][1];
                out[oc * HW + gy * IMGW + gx0 + 8] = acc[i][j][2];
                out[(oc + 1) * HW + gy * IMGW + gx0 + 8] = acc[i][j][3];
            }
        }
    }
}

__device__ __forceinline__ float4 l2n(float4 a) {
    float n = sqrtf(a.x * a.x + a.y * a.y + a.z * a.z + a.w * a.w);
    float inv = 1.f / fmaxf(n, 1e-12f);
    a.x *= inv; a.y *= inv; a.z *= inv; a.w *= inv;
    return a;
}

__device__ __forceinline__ void store_y_pair(int pair, int ppos, float a, float b) {
    __nv_bfloat16 ha = __float2bfloat16_rn(a), hb = __float2bfloat16_rn(b);
    __nv_bfloat162 hh; hh.x = ha; hh.y = hb;
    g_ya_hi[pair * PHW + ppos] = *(unsigned*)&hh;
    g_ya_lo[pair * PHW + ppos] =
        pack_bf2(a - __bfloat162float(ha), b - __bfloat162float(hb));
}

// NHWC q fetch: one float4 at g_conv1[pos*288 + 256 + n*4], normalized+scaled.
__device__ __forceinline__ void load_q(int n, int pos, float sc,
                                       unsigned long long& qxy,
                                       unsigned long long& qzw) {
    float4 q = *(const float4*)(g_conv1 + pos * 288 + 256 + n * 4);
    q = l2n(q);
    qxy = pk2(q.x * sc, q.y * sc);
    qzw = pk2(q.z * sc, q.w * sc);
}

// ---------------------------------------------------------------------------
// Attention launch #1: heavy axial ROW blocks (bx<1920, 2 q/thread) first,
// then WINDOW blocks (branches 0,1). All q/k/v reads are single float4 LDGs
// from NHWC g_conv1.
// ---------------------------------------------------------------------------
__global__ __launch_bounds__(256) void attn_winrow_kernel(
    const float* __restrict__ ls, const float* __restrict__ lrls) {
    __shared__ ulonglong2 s_k2[240];
    __shared__ ulonglong2 s_v2[240];
    __shared__ float s_sc[8];
    const int bx = blockIdx.x;
    const int t = threadIdx.x;

    if (bx >= 1920) {
        // ---- window attention ----
        const int wb = bx - 1920;
        const int branch = wb / 2304;
        const int win = wb - branch * 2304;
        const int Hw = win / 48, Ww = win % 48;
        if (t < 8) s_sc[t] = expf(fminf(ls[t], LOG_MAX));

        const int n = t / 25, tok = t % 25;
        const int wy = tok / 5, wx = tok % 5;
        const int py = Hw * 5 + wy, px = Ww * 5 + wx;
        int gy = py, gx = px;
        if (branch) { gy = (gy + 3) % IMGW; gx = (gx + 3) % IMGW; }
        const int pos = gy * IMGW + gx;

        if (t < 200) {
            const float* base = g_conv1 + pos * 288 + branch * 64 + n * 4;
            float4 kk = *(const float4*)base;
            float4 vv = *(const float4*)(base + 32);
            kk = l2n(kk);
            s_k2[n * 25 + tok] = make_ulonglong2(pk2(kk.x, kk.y), pk2(kk.z, kk.w));
            s_v2[n * 25 + tok] = make_ulonglong2(pk2(vv.x, vv.y), pk2(vv.z, vv.w));
        }
        __syncthreads();
        if (t >= 200) return;

        float4 q = *(const float4*)(g_conv1 + pos * 288 + 192 + branch * 32 + n * 4);
        q = l2n(q);
        const float sc = s_sc[n];
        const unsigned long long qxy = pk2(q.x * sc, q.y * sc);
        const unsigned long long qzw = pk2(q.z * sc, q.w * sc);

        float l = 0.f;
        unsigned long long axy = 0ull, azw = 0ull;
#pragma unroll
        for (int j = 0; j < 25; j++) {
            ulonglong2 kj = s_k2[n * 25 + j];
            ulonglong2 vj = s_v2[n * 25 + j];
            float2 ss = upk2(fma2(qzw, kj.y, mul2(qxy, kj.x)));
            float wgt = __expf(ss.x + ss.y);
            unsigned long long ww = pk2(wgt, wgt);
            axy = fma2(ww, vj.x, axy);
            azw = fma2(ww, vj.y, azw);
            l += wgt;
        }
        float invl = 1.f / l;
        float2 a01 = upk2(axy), a23 = upk2(azw);

        int oy = py, ox = px;
        if (branch) { oy = (oy + 2) % IMGW; ox = (ox + 2) % IMGW; }
        const int ppos = (oy + 1) * PW + (ox + 1);
        const int pair0 = branch * 16 + 2 * n;
        store_y_pair(pair0,     ppos, a01.x * invl, a01.y * invl);
        store_y_pair(pair0 + 1, ppos, a23.x * invl, a23.y * invl);
        return;
    }

    // ---- axial row attention: 2 queries/thread ----
    const int n = bx / IMGW, h = bx % IMGW;
    if (t == 0) s_sc[0] = expf(fminf(lrls[n], LOG_MAX));

    if (t < 240) {
        const int pos = h * IMGW + t;
        const float* base = g_conv1 + pos * 288 + 128 + n * 4;
        float4 kk = *(const float4*)base;
        float4 vv = *(const float4*)(base + 32);
        kk = l2n(kk);
        s_k2[t] = make_ulonglong2(pk2(kk.x, kk.y), pk2(kk.z, kk.w));
        s_v2[t] = make_ulonglong2(pk2(vv.x, vv.y), pk2(vv.z, vv.w));
    }
    __syncthreads();
    if (t >= 120) return;

    const float sc = s_sc[0];
    const int posA = h * IMGW + t, posB = posA + 120;
    unsigned long long qxyA, qzwA, qxyB, qzwB;
    load_q(n, posA, sc, qxyA, qzwA);
    load_q(n, posB, sc, qxyB, qzwB);

    float lA = 0.f, lB = 0.f;
    unsigned long long axyA = 0ull, azwA = 0ull, axyB = 0ull, azwB = 0ull;
#pragma unroll 2
    for (int j = 0; j < 240; j++) {
        ulonglong2 kj = s_k2[j];
        ulonglong2 vj = s_v2[j];
        float2 sA = upk2(fma2(qzwA, kj.y, mul2(qxyA, kj.x)));
        float2 sB = upk2(fma2(qzwB, kj.y, mul2(qxyB, kj.x)));
        float wA = __expf(sA.x + sA.y);
        float wB = __expf(sB.x + sB.y);
        unsigned long long wwA = pk2(wA, wA);
        unsigned long long wwB = pk2(wB, wB);
        axyA = fma2(wwA, vj.x, axyA);
        azwA = fma2(wwA, vj.y, azwA);
        axyB = fma2(wwB, vj.x, axyB);
        azwB = fma2(wwB, vj.y, azwB);
        lA += wA;
        lB += wB;
    }
    float iA = 1.f / lA, iB = 1.f / lB;
    float2 a01A = upk2(axyA), a23A = upk2(azwA);
    float2 a01B = upk2(axyB), a23B = upk2(azwB);
    *(float4*)(g_v1 + posA * 32 + n * 4) =
        make_float4(a01A.x * iA, a01A.y * iA, a23A.x * iA, a23A.y * iA);
    *(float4*)(g_v1 + posB * 32 + n * 4) =
        make_float4(a01B.x * iB, a01B.y * iB, a23B.x * iB, a23B.y * iB);
}

// ---------------------------------------------------------------------------
// Axial column attention: 2 queries/thread, 128-thread blocks, NHWC reads.
// ---------------------------------------------------------------------------
__global__ __launch_bounds__(128) void axial_col_kernel(const float* __restrict__ lrls) {
    const int n = blockIdx.x / IMGW, w = blockIdx.x % IMGW;
    const int t = threadIdx.x;
    __shared__ ulonglong2 s_k2[240];
    __shared__ ulonglong2 s_v2[240];
    __shared__ float s_sc;
    if (t == 0) s_sc = expf(fminf(lrls[n], LOG_MAX));

    for (int i = t; i < 240; i += 128) {
        const int pos = i * IMGW + w;
        float4 kk = *(const float4*)(g_conv1 + pos * 288 + 128 + n * 4);
        float4 vv = *(const float4*)(g_v1 + pos * 32 + n * 4);
        kk = l2n(kk);
        s_k2[i] = make_ulonglong2(pk2(kk.x, kk.y), pk2(kk.z, kk.w));
        s_v2[i] = make_ulonglong2(pk2(vv.x, vv.y), pk2(vv.z, vv.w));
    }
    __syncthreads();
    if (t >= 120) return;

    const float sc = s_sc;
    const int posA = t * IMGW + w, posB = (t + 120) * IMGW + w;
    unsigned long long qxyA, qzwA, qxyB, qzwB;
    load_q(n, posA, sc, qxyA, qzwA);
    load_q(n, posB, sc, qxyB, qzwB);

    float lA = 0.f, lB = 0.f;
    unsigned long long axyA = 0ull, azwA = 0ull, axyB = 0ull, azwB = 0ull;
#pragma unroll 2
    for (int j = 0; j < 240; j++) {
        ulonglong2 kj = s_k2[j];
        ulonglong2 vj = s_v2[j];
        float2 sA = upk2(fma2(qzwA, kj.y, mul2(qxyA, kj.x)));
        float2 sB = upk2(fma2(qzwB, kj.y, mul2(qxyB, kj.x)));
        float wA = __expf(sA.x + sA.y);
        float wB = __expf(sB.x + sB.y);
        unsigned long long wwA = pk2(wA, wA);
        unsigned long long wwB = pk2(wB, wB);
        axyA = fma2(wwA, vj.x, axyA);
        azwA = fma2(wwA, vj.y, azwA);
        axyB = fma2(wwB, vj.x, axyB);
        azwB = fma2(wwB, vj.y, azwB);
        lA += wA;
        lB += wB;
    }
    float iA = 1.f / lA, iB = 1.f / lB;
    float2 a01A = upk2(axyA), a23A = upk2(azwA);
    float2 a01B = upk2(axyB), a23B = upk2(azwB);
    const int pair0 = 32 + 2 * n;
    const int pposA = (t + 1) * PW + (w + 1);
    const int pposB = (t + 121) * PW + (w + 1);
    store_y_pair(pair0,     pposA, a01A.x * iA, a01A.y * iA);
    store_y_pair(pair0 + 1, pposA, a23A.x * iA, a23A.y * iA);
    store_y_pair(pair0,     pposB, a01B.x * iB, a01B.y * iB);
    store_y_pair(pair0 + 1, pposB, a23B.x * iB, a23B.y * iB);
}

// ---------------------------------------------------------------------------
extern "C" void kernel_launch(void* const* d_in, const int* in_sizes, int n_in,
                              void* d_out, int out_size) {
    const float* x      = (const float*)d_in[0];
    const float* w_in   = (const float*)d_in[1];
    const float* b_in   = (const float*)d_in[2];
    const float* w_f    = (const float*)d_in[3];
    const float* b_f    = (const float*)d_in[4];
    const float* w_out  = (const float*)d_in[5];
    const float* b_out  = (const float*)d_in[6];
    const float* ls     = (const float*)d_in[7];
    const float* lr_ls  = (const float*)d_in[8];
    float* out = (float*)d_out;

    float* p_conv1; unsigned* p_wrep; float* p_bias;
    unsigned *p_xh, *p_xl, *p_yh, *p_yl;
    cudaGetSymbolAddress((void**)&p_conv1, g_conv1);
    cudaGetSymbolAddress((void**)&p_wrep, g_wrep);
    cudaGetSymbolAddress((void**)&p_bias, g_bias);
    cudaGetSymbolAddress((void**)&p_xh, g_xa_hi);
    cudaGetSymbolAddress((void**)&p_xl, g_xa_lo);
    cudaGetSymbolAddress((void**)&p_yh, g_ya_hi);
    cudaGetSymbolAddress((void**)&p_yl, g_ya_lo);

    const int SMEM_BYTES = 20224 * 4;
    static int attr_set = 0;
    if (!attr_set) {
        cudaFuncSetAttribute(conv3x3_mma_kernel,
                             cudaFuncAttributeMaxDynamicSharedMemorySize, SMEM_BYTES);
        attr_set = 1;
    }

    const int NTOT = NPREP_X + NPREP_B + 288 + NREPACK;
    prep_repack_kernel<<<(NTOT + 255) / 256, 256>>>(x, b_in, b_f, w_in, w_f, w_out);

    // fused conv_in+conv_f -> NHWC g_conv1
    conv3x3_mma_kernel<<<dim3(15, 30, 3), 256, SMEM_BYTES>>>(p_xh, p_xl, p_wrep,
                                                             p_bias, p_conv1, 288, 1);

    attn_winrow_kernel<<<1920 + 4608, 256>>>(ls, lr_ls);
    axial_col_kernel<<<8 * IMGW, 128>>>(lr_ls);

    unsigned* wrep_out = p_wrep + 2 * 288 * 432;
    // conv_out -> planar harness output
    conv3x3_mma_kernel<<<dim3(15, 30, 1), 256, SMEM_BYTES>>>(p_yh, p_yl, wrep_out,
                                                             b_out, out, 96, 0);
}

// round 15
// speedup vs baseline: 1.2471x; 1.0012x over previous
#include <cuda_runtime.h>
#include <cuda_bf16.h>
#include <math.h>

#define HW    57600
#define IMGW  240
#define PW    244
#define PH    242
#define PHW   (PH * PW)      // 59048
#define LOG_MAX 4.6051701859880914f

// Scratch (allocation-free):
__device__ float    g_conv1[288 * HW];     // NHWC: [pos][ch], stride 288
__device__ float    g_v1[32 * HW];         // NHWC: [pos][ch], stride 32
__device__ unsigned g_wrep[768 * 864];
__device__ float    g_bias[288];
__device__ unsigned g_xa_hi[48 * PHW];
__device__ unsigned g_xa_lo[48 * PHW];
__device__ unsigned g_ya_hi[48 * PHW];
__device__ unsigned g_ya_lo[48 * PHW];

__device__ __forceinline__ unsigned pack_bf2(float a, float b) {
    __nv_bfloat162 h;
    h.x = __float2bfloat16_rn(a);
    h.y = __float2bfloat16_rn(b);
    return *(unsigned*)&h;
}
__device__ __forceinline__ unsigned smem_u32(const void* p) {
    return (unsigned)__cvta_generic_to_shared(p);
}
#define CP16(dst, src) asm volatile("cp.async.cg.shared.global [%0], [%1], 16;" :: "r"(dst), "l"(src))
#define CP8(dst, src)  asm volatile("cp.async.ca.shared.global [%0], [%1], 8;"  :: "r"(dst), "l"(src))
#define CP_COMMIT()    asm volatile("cp.async.commit_group;" ::: "memory")
#define CP_WAIT2()     asm volatile("cp.async.wait_group 2;" ::: "memory")

// ---- packed f32x2 helpers ----
__device__ __forceinline__ unsigned long long mul2(unsigned long long a,
                                                   unsigned long long b) {
    unsigned long long d;
    asm("mul.rn.f32x2 %0, %1, %2;" : "=l"(d) : "l"(a), "l"(b));
    return d;
}
__device__ __forceinline__ unsigned long long fma2(unsigned long long a,
                                                   unsigned long long b,
                                                   unsigned long long c) {
    unsigned long long d;
    asm("fma.rn.f32x2 %0, %1, %2, %3;" : "=l"(d) : "l"(a), "l"(b), "l"(c));
    return d;
}
__device__ __forceinline__ unsigned long long pk2(float lo, float hi) {
    unsigned long long r;
    asm("mov.b64 %0, {%1,%2};" : "=l"(r) : "f"(lo), "f"(hi));
    return r;
}
__device__ __forceinline__ float2 upk2(unsigned long long v) {
    float2 f;
    asm("mov.b64 {%0,%1}, %2;" : "=f"(f.x), "=f"(f.y) : "l"(v));
    return f;
}

// ---------------------------------------------------------------------------
// Fused prep + weight repack in ONE launch.
// ---------------------------------------------------------------------------
#define NPREP_X (48 * PHW)
#define NPREP_B (48 * (2 * PW + 4 * 240))
#define NREPACK (384 * 432)

__device__ __forceinline__ void repack_one(const float* wt, unsigned* wrep,
                                           int idx, int CoutLocal, int ocOff,
                                           int CoutTotal) {
    int o = idx % CoutLocal;
    int rem = idx / CoutLocal;
    int p = rem % 8; int rem2 = rem / 8;
    int s = rem2 % 9;
    int ch = rem2 / 9;
    int ic = ch * 16 + 2 * p;
    float v0 = wt[(o * 96 + ic) * 9 + s];
    float v1 = wt[(o * 96 + ic + 1) * 9 + s];
    __nv_bfloat16 h0 = __float2bfloat16_rn(v0);
    __nv_bfloat16 h1 = __float2bfloat16_rn(v1);
    __nv_bfloat162 hi; hi.x = h0; hi.y = h1;
    int dst = rem * CoutTotal + ocOff + o;
    wrep[dst] = *(unsigned*)&hi;
    wrep[CoutTotal * 432 + dst] =
        pack_bf2(v0 - __bfloat162float(h0), v1 - __bfloat162float(h1));
}

__global__ void prep_repack_kernel(const float* __restrict__ x,
                                   const float* __restrict__ b_in,
                                   const float* __restrict__ b_f,
                                   const float* __restrict__ w_in,
                                   const float* __restrict__ w_f,
                                   const float* __restrict__ w_out) {
    int idx = blockIdx.x * 256 + threadIdx.x;
    if (idx < NPREP_X) {
        int p = idx / PHW, rem = idx % PHW;
        int py = rem / PW, px = rem % PW;
        float v0 = 0.f, v1 = 0.f;
        if (py >= 1 && py <= 240 && px >= 1 && px <= 240) {
            int pos = (py - 1) * IMGW + (px - 1);
            v0 = x[(2 * p) * HW + pos];
            v1 = x[(2 * p + 1) * HW + pos];
        }
        __nv_bfloat16 h0 = __float2bfloat16_rn(v0);
        __nv_bfloat16 h1 = __float2bfloat16_rn(v1);
        __nv_bfloat162 hh; hh.x = h0; hh.y = h1;
        g_xa_hi[idx] = *(unsigned*)&hh;
        g_xa_lo[idx] = pack_bf2(v0 - __bfloat162float(h0), v1 - __bfloat162float(h1));
        return;
    }
    idx -= NPREP_X;
    if (idx < NPREP_B) {
        const int PER = 2 * PW + 4 * 240;
        int p = idx / PER, j = idx % PER;
        int py, px;
        if (j < 2 * PW) { py = (j / PW) ? 241 : 0; px = j % PW; }
        else {
            int k = j - 2 * PW;
            py = 1 + (k % 240);
            int c = k / 240;
            px = (c == 0) ? 0 : 240 + c;
        }
        int o = p * PHW + py * PW + px;
        g_ya_hi[o] = 0u;
        g_ya_lo[o] = 0u;
        return;
    }
    idx -= NPREP_B;
    if (idx < 288) {
        g_bias[idx] = idx < 192 ? b_in[idx] : b_f[idx - 192];
        return;
    }
    idx -= 288;
    const int T1 = 192 * 432, T2 = 96 * 432;
    if (idx < T1) { repack_one(w_in, g_wrep, idx, 192, 0, 288); return; }
    idx -= T1;
    if (idx < T2) { repack_one(w_f, g_wrep, idx, 96, 192, 288); return; }
    idx -= T2;
    if (idx < T2) repack_one(w_out, g_wrep + 2 * 288 * 432, idx, 96, 0, 96);
}

// ---------------------------------------------------------------------------
// Implicit-GEMM 3x3 conv (best-known pipeline). out_nhwc: 0 = planar
// (oc*HW+pos, for final output), 1 = NHWC pos*288+oc (for g_conv1).
// ---------------------------------------------------------------------------
__global__ __launch_bounds__(256, 2) void conv3x3_mma_kernel(
    const unsigned* __restrict__ in_hi, const unsigned* __restrict__ in_lo,
    const unsigned* __restrict__ wrep, const float* __restrict__ bias,
    float* __restrict__ out, int Cout, int out_nhwc) {
    extern __shared__ unsigned smem[];
    unsigned* s_b_hi = smem + 6400;
    unsigned* s_b_lo = smem + 13312;

    const int tid = threadIdx.x;
    const int lane = tid & 31, w = tid >> 5;
    const int wm = w & 1, wn = w >> 1;
    const int x0 = blockIdx.x * 16, y0 = blockIdx.y * 8;
    const int oc_blk = blockIdx.z * 96;
    const int g = lane >> 2, t = lane & 3;
    const int wlo = Cout * 432;

    auto stage_a = [&](int ch, int buf) {
        unsigned* a_base = smem + buf * 3200;
        for (int i = tid; i < 800; i += 256) {
            int p = i / 100, r = i % 100;
            int ly = r / 10, seg = r % 10;
            int is_lo = seg >= 5, s5 = seg - is_lo * 5;
            int lx = s5 * 4;
            const unsigned* src = (is_lo ? in_lo : in_hi) +
                                  (ch * 8 + p) * PHW + (y0 + ly) * PW + x0 + lx;
            unsigned dst = smem_u32(a_base + is_lo * 1600 + p * 200 + ly * 20 + lx);
            if (s5 < 4) CP16(dst, src);
            else        CP8(dst, src);
        }
    };
    auto stage_b_rows = [&](int ch, int r0, int nrows) {
        int half = nrows * 24;
        for (int i = tid; i < half * 2; i += 256) {
            int is_lo = i >= half, k = i - is_lo * half;
            int r = r0 + k / 24, c = k % 24;
            const unsigned* src = wrep + is_lo * wlo +
                                  (ch * 72 + r) * Cout + oc_blk + c * 4;
            int col = (c * 4) ^ ((r & 3) * 8);
            unsigned dst = smem_u32((is_lo ? s_b_lo : s_b_hi) + r * 96 + col);
            CP16(dst, src);
        }
    };

    float acc[4][3][4];
#pragma unroll
    for (int j = 0; j < 3; j++) {
        int oc = oc_blk + wn * 24 + j * 8 + 2 * t;
        float b0 = bias[oc], b1 = bias[oc + 1];
#pragma unroll
        for (int i = 0; i < 4; i++) {
            acc[i][j][0] = b0; acc[i][j][1] = b1;
            acc[i][j][2] = b0; acc[i][j][3] = b1;
        }
    }

    stage_a(0, 0);           CP_COMMIT();
    stage_b_rows(0, 0, 40);  CP_COMMIT();
    stage_b_rows(0, 40, 32); CP_COMMIT();

    const unsigned* a_hi;
    const unsigned* a_lo;
    auto compute_shift = [&](int s) {
        const int dy = s / 3, dx = s % 3;
        unsigned bh[3][2], bl[3][2];
        const int swz = t * 8;
#pragma unroll
        for (int j = 0; j < 3; j++) {
            int oc = (wn * 24 + j * 8 + g) ^ swz;
            bh[j][0] = s_b_hi[(s * 8 + t) * 96 + oc];
            bh[j][1] = s_b_hi[(s * 8 + t + 4) * 96 + oc];
            bl[j][0] = s_b_lo[(s * 8 + t) * 96 + oc];
            bl[j][1] = s_b_lo[(s * 8 + t + 4) * 96 + oc];
        }
#pragma unroll
        for (int i = 0; i < 4; i++) {
            int py = wm * 4 + i;
            int o00 = t * 200 + (py + dy) * 20 + g + dx;
            int o4  = o00 + 800;
            unsigned ah0 = a_hi[o00], ah1 = a_hi[o00 + 8];
            unsigned ah2 = a_hi[o4],  ah3 = a_hi[o4 + 8];
            unsigned al0 = a_lo[o00], al1 = a_lo[o00 + 8];
            unsigned al2 = a_lo[o4],  al3 = a_lo[o4 + 8];
#pragma unroll
            for (int j = 0; j < 3; j++) {
                asm volatile(
                    "mma.sync.aligned.m16n8k16.row.col.f32.bf16.bf16.f32 "
                    "{%0,%1,%2,%3}, {%4,%5,%6,%7}, {%8,%9}, {%0,%1,%2,%3};"
                    : "+f"(acc[i][j][0]), "+f"(acc[i][j][1]),
                      "+f"(acc[i][j][2]), "+f"(acc[i][j][3])
                    : "r"(al0), "r"(al1), "r"(al2), "r"(al3),
                      "r"(bh[j][0]), "r"(bh[j][1]));
                asm volatile(
                    "mma.sync.aligned.m16n8k16.row.col.f32.bf16.bf16.f32 "
                    "{%0,%1,%2,%3}, {%4,%5,%6,%7}, {%8,%9}, {%0,%1,%2,%3};"
                    : "+f"(acc[i][j][0]), "+f"(acc[i][j][1]),
                      "+f"(acc[i][j][2]), "+f"(acc[i][j][3])
                    : "r"(ah0), "r"(ah1), "r"(ah2), "r"(ah3),
                      "r"(bl[j][0]), "r"(bl[j][1]));
                asm volatile(
                    "mma.sync.aligned.m16n8k16.row.col.f32.bf16.bf16.f32 "
                    "{%0,%1,%2,%3}, {%4,%5,%6,%7}, {%8,%9}, {%0,%1,%2,%3};"
                    : "+f"(acc[i][j][0]), "+f"(acc[i][j][1]),
                      "+f"(acc[i][j][2]), "+f"(acc[i][j][3])
                    : "r"(ah0), "r"(ah1), "r"(ah2), "r"(ah3),
                      "r"(bh[j][0]), "r"(bh[j][1]));
            }
        }
    };

    for (int ch = 0; ch < 6; ch++) {
        if (ch < 5) stage_a(ch + 1, (ch + 1) & 1);
        CP_COMMIT();
        CP_WAIT2();
        __syncthreads();

        a_hi = smem + (ch & 1) * 3200;
        a_lo = a_hi + 1600;
#pragma unroll
        for (int s = 0; s < 5; s++) compute_shift(s);
        __syncthreads();

        if (ch < 5) stage_b_rows(ch + 1, 0, 40);
        CP_COMMIT();
        CP_WAIT2();
        __syncthreads();
#pragma unroll
        for (int s = 5; s < 9; s++) compute_shift(s);
        __syncthreads();

        if (ch < 5) stage_b_rows(ch + 1, 40, 32);
        CP_COMMIT();
    }

    const int gx0 = x0 + g;
    if (out_nhwc) {
#pragma unroll
        for (int i = 0; i < 4; i++) {
            int gy = y0 + wm * 4 + i;
            float* r0 = out + (gy * IMGW + gx0) * 288;
            float* r8 = r0 + 8 * 288;
#pragma unroll
            for (int j = 0; j < 3; j++) {
                int oc = oc_blk + wn * 24 + j * 8 + 2 * t;
                *(float2*)(r0 + oc) = make_float2(acc[i][j][0], acc[i][j][1]);
                *(float2*)(r8 + oc) = make_float2(acc[i][j][2], acc[i][j][3]);
            }
        }
    } else {
#pragma unroll
        for (int i = 0; i < 4; i++) {
            int gy = y0 + wm * 4 + i;
#pragma unroll
            for (int j = 0; j < 3; j++) {
                int oc = oc_blk + wn * 24 + j * 8 + 2 * t;
                out[oc * HW + gy * IMGW + gx0] = acc[i][j][0];
                out[(oc + 1) * HW + gy * IMGW + gx0] = acc[i][j][1];
                out[oc * HW + gy * IMGW + gx0 + 8] = acc[i][j][2];
                out[(oc + 1) * HW + gy * IMGW + gx0 + 8] = acc[i][j][3];
            }
        }
    }
}

__device__ __forceinline__ float4 l2n(float4 a) {
    float n = sqrtf(a.x * a.x + a.y * a.y + a.z * a.z + a.w * a.w);
    float inv = 1.f / fmaxf(n, 1e-12f);
    a.x *= inv; a.y *= inv; a.z *= inv; a.w *= inv;
    return a;
}

__device__ __forceinline__ void store_y_pair(int pair, int ppos, float a, float b) {
    __nv_bfloat16 ha = __float2bfloat16_rn(a), hb = __float2bfloat16_rn(b);
    __nv_bfloat162 hh; hh.x = ha; hh.y = hb;
    g_ya_hi[pair * PHW + ppos] = *(unsigned*)&hh;
    g_ya_lo[pair * PHW + ppos] =
        pack_bf2(a - __bfloat162float(ha), b - __bfloat162float(hb));
}

// NHWC q fetch: one float4 at g_conv1[pos*288 + 256 + n*4], normalized+scaled.
__device__ __forceinline__ void load_q(int n, int pos, float sc,
                                       unsigned long long& qxy,
                                       unsigned long long& qzw) {
    float4 q = *(const float4*)(g_conv1 + pos * 288 + 256 + n * 4);
    q = l2n(q);
    qxy = pk2(q.x * sc, q.y * sc);
    qzw = pk2(q.z * sc, q.w * sc);
}

// ---------------------------------------------------------------------------
// Attention launch #1: heavy axial ROW blocks (bx<1920, 2 q/thread) first,
// then WINDOW blocks (branches 0,1). All q/k/v reads are single float4 LDGs
// from NHWC g_conv1.
// ---------------------------------------------------------------------------
__global__ __launch_bounds__(256) void attn_winrow_kernel(
    const float* __restrict__ ls, const float* __restrict__ lrls) {
    __shared__ ulonglong2 s_k2[240];
    __shared__ ulonglong2 s_v2[240];
    __shared__ float s_sc[8];
    const int bx = blockIdx.x;
    const int t = threadIdx.x;

    if (bx >= 1920) {
        // ---- window attention ----
        const int wb = bx - 1920;
        const int branch = wb / 2304;
        const int win = wb - branch * 2304;
        const int Hw = win / 48, Ww = win % 48;
        if (t < 8) s_sc[t] = expf(fminf(ls[t], LOG_MAX));

        const int n = t / 25, tok = t % 25;
        const int wy = tok / 5, wx = tok % 5;
        const int py = Hw * 5 + wy, px = Ww * 5 + wx;
        int gy = py, gx = px;
        if (branch) { gy = (gy + 3) % IMGW; gx = (gx + 3) % IMGW; }
        const int pos = gy * IMGW + gx;

        if (t < 200) {
            const float* base = g_conv1 + pos * 288 + branch * 64 + n * 4;
            float4 kk = *(const float4*)base;
            float4 vv = *(const float4*)(base + 32);
            kk = l2n(kk);
            s_k2[n * 25 + tok] = make_ulonglong2(pk2(kk.x, kk.y), pk2(kk.z, kk.w));
            s_v2[n * 25 + tok] = make_ulonglong2(pk2(vv.x, vv.y), pk2(vv.z, vv.w));
        }
        __syncthreads();
        if (t >= 200) return;

        float4 q = *(const float4*)(g_conv1 + pos * 288 + 192 + branch * 32 + n * 4);
        q = l2n(q);
        const float sc = s_sc[n];
        const unsigned long long qxy = pk2(q.x * sc, q.y * sc);
        const unsigned long long qzw = pk2(q.z * sc, q.w * sc);

        float l = 0.f;
        unsigned long long axy = 0ull, azw = 0ull;
#pragma unroll
        for (int j = 0; j < 25; j++) {
            ulonglong2 kj = s_k2[n * 25 + j];
            ulonglong2 vj = s_v2[n * 25 + j];
            float2 ss = upk2(fma2(qzw, kj.y, mul2(qxy, kj.x)));
            float wgt = __expf(ss.x + ss.y);
            unsigned long long ww = pk2(wgt, wgt);
            axy = fma2(ww, vj.x, axy);
            azw = fma2(ww, vj.y, azw);
            l += wgt;
        }
        float invl = 1.f / l;
        float2 a01 = upk2(axy), a23 = upk2(azw);

        int oy = py, ox = px;
        if (branch) { oy = (oy + 2) % IMGW; ox = (ox + 2) % IMGW; }
        const int ppos = (oy + 1) * PW + (ox + 1);
        const int pair0 = branch * 16 + 2 * n;
        store_y_pair(pair0,     ppos, a01.x * invl, a01.y * invl);
        store_y_pair(pair0 + 1, ppos, a23.x * invl, a23.y * invl);
        return;
    }

    // ---- axial row attention: 2 queries/thread ----
    const int n = bx / IMGW, h = bx % IMGW;
    if (t == 0) s_sc[0] = expf(fminf(lrls[n], LOG_MAX));

    if (t < 240) {
        const int pos = h * IMGW + t;
        const float* base = g_conv1 + pos * 288 + 128 + n * 4;
        float4 kk = *(const float4*)base;
        float4 vv = *(const float4*)(base + 32);
        kk = l2n(kk);
        s_k2[t] = make_ulonglong2(pk2(kk.x, kk.y), pk2(kk.z, kk.w));
        s_v2[t] = make_ulonglong2(pk2(vv.x, vv.y), pk2(vv.z, vv.w));
    }
    __syncthreads();
    if (t >= 120) return;

    const float sc = s_sc[0];
    const int posA = h * IMGW + t, posB = posA + 120;
    unsigned long long qxyA, qzwA, qxyB, qzwB;
    load_q(n, posA, sc, qxyA, qzwA);
    load_q(n, posB, sc, qxyB, qzwB);

    float lA = 0.f, lB = 0.f;
    unsigned long long axyA = 0ull, azwA = 0ull, axyB = 0ull, azwB = 0ull;
#pragma unroll 2
    for (int j = 0; j < 240; j++) {
        ulonglong2 kj = s_k2[j];
        ulonglong2 vj = s_v2[j];
        float2 sA = upk2(fma2(qzwA, kj.y, mul2(qxyA, kj.x)));
        float2 sB = upk2(fma2(qzwB, kj.y, mul2(qxyB, kj.x)));
        float wA = __expf(sA.x + sA.y);
        float wB = __expf(sB.x + sB.y);
        unsigned long long wwA = pk2(wA, wA);
        unsigned long long wwB = pk2(wB, wB);
        axyA = fma2(wwA, vj.x, axyA);
        azwA = fma2(wwA, vj.y, azwA);
        axyB = fma2(wwB, vj.x, axyB);
        azwB = fma2(wwB, vj.y, azwB);
        lA += wA;
        lB += wB;
    }
    float iA = 1.f / lA, iB = 1.f / lB;
    float2 a01A = upk2(axyA), a23A = upk2(azwA);
    float2 a01B = upk2(axyB), a23B = upk2(azwB);
    *(float4*)(g_v1 + posA * 32 + n * 4) =
        make_float4(a01A.x * iA, a01A.y * iA, a23A.x * iA, a23A.y * iA);
    *(float4*)(g_v1 + posB * 32 + n * 4) =
        make_float4(a01B.x * iB, a01B.y * iB, a23B.x * iB, a23B.y * iB);
}

// ---------------------------------------------------------------------------
// Axial column attention: 2 queries/thread, 128-thread blocks, NHWC reads.
// ---------------------------------------------------------------------------
__global__ __launch_bounds__(128) void axial_col_kernel(const float* __restrict__ lrls) {
    const int n = blockIdx.x / IMGW, w = blockIdx.x % IMGW;
    const int t = threadIdx.x;
    __shared__ ulonglong2 s_k2[240];
    __shared__ ulonglong2 s_v2[240];
    __shared__ float s_sc;
    if (t == 0) s_sc = expf(fminf(lrls[n], LOG_MAX));

    for (int i = t; i < 240; i += 128) {
        const int pos = i * IMGW + w;
        float4 kk = *(const float4*)(g_conv1 + pos * 288 + 128 + n * 4);
        float4 vv = *(const float4*)(g_v1 + pos * 32 + n * 4);
        kk = l2n(kk);
        s_k2[i] = make_ulonglong2(pk2(kk.x, kk.y), pk2(kk.z, kk.w));
        s_v2[i] = make_ulonglong2(pk2(vv.x, vv.y), pk2(vv.z, vv.w));
    }
    __syncthreads();
    if (t >= 120) return;

    const float sc = s_sc;
    const int posA = t * IMGW + w, posB = (t + 120) * IMGW + w;
    unsigned long long qxyA, qzwA, qxyB, qzwB;
    load_q(n, posA, sc, qxyA, qzwA);
    load_q(n, posB, sc, qxyB, qzwB);

    float lA = 0.f, lB = 0.f;
    unsigned long long axyA = 0ull, azwA = 0ull, axyB = 0ull, azwB = 0ull;
#pragma unroll 2
    for (int j = 0; j < 240; j++) {
        ulonglong2 kj = s_k2[j];
        ulonglong2 vj = s_v2[j];
        float2 sA = upk2(fma2(qzwA, kj.y, mul2(qxyA, kj.x)));
        float2 sB = upk2(fma2(qzwB, kj.y, mul2(qxyB, kj.x)));
        float wA = __expf(sA.x + sA.y);
        float wB = __expf(sB.x + sB.y);
        unsigned long long wwA = pk2(wA, wA);
        unsigned long long wwB = pk2(wB, wB);
        axyA = fma2(wwA, vj.x, axyA);
        azwA = fma2(wwA, vj.y, azwA);
        axyB = fma2(wwB, vj.x, axyB);
        azwB = fma2(wwB, vj.y, azwB);
        lA += wA;
        lB += wB;
    }
    float iA = 1.f / lA, iB = 1.f / lB;
    float2 a01A = upk2(axyA), a23A = upk2(azwA);
    float2 a01B = upk2(axyB), a23B = upk2(azwB);
    const int pair0 = 32 + 2 * n;
    const int pposA = (t + 1) * PW + (w + 1);
    const int pposB = (t + 121) * PW + (w + 1);
    store_y_pair(pair0,     pposA, a01A.x * iA, a01A.y * iA);
    store_y_pair(pair0 + 1, pposA, a23A.x * iA, a23A.y * iA);
    store_y_pair(pair0,     pposB, a01B.x * iB, a01B.y * iB);
    store_y_pair(pair0 + 1, pposB, a23B.x * iB, a23B.y * iB);
}

// ---------------------------------------------------------------------------
extern "C" void kernel_launch(void* const* d_in, const int* in_sizes, int n_in,
                              void* d_out, int out_size) {
    const float* x      = (const float*)d_in[0];
    const float* w_in   = (const float*)d_in[1];
    const float* b_in   = (const float*)d_in[2];
    const float* w_f    = (const float*)d_in[3];
    const float* b_f    = (const float*)d_in[4];
    const float* w_out  = (const float*)d_in[5];
    const float* b_out  = (const float*)d_in[6];
    const float* ls     = (const float*)d_in[7];
    const float* lr_ls  = (const float*)d_in[8];
    float* out = (float*)d_out;

    float* p_conv1; unsigned* p_wrep; float* p_bias;
    unsigned *p_xh, *p_xl, *p_yh, *p_yl;
    cudaGetSymbolAddress((void**)&p_conv1, g_conv1);
    cudaGetSymbolAddress((void**)&p_wrep, g_wrep);
    cudaGetSymbolAddress((void**)&p_bias, g_bias);
    cudaGetSymbolAddress((void**)&p_xh, g_xa_hi);
    cudaGetSymbolAddress((void**)&p_xl, g_xa_lo);
    cudaGetSymbolAddress((void**)&p_yh, g_ya_hi);
    cudaGetSymbolAddress((void**)&p_yl, g_ya_lo);

    const int SMEM_BYTES = 20224 * 4;
    static int attr_set = 0;
    if (!attr_set) {
        cudaFuncSetAttribute(conv3x3_mma_kernel,
                             cudaFuncAttributeMaxDynamicSharedMemorySize, SMEM_BYTES);
        attr_set = 1;
    }

    const int NTOT = NPREP_X + NPREP_B + 288 + NREPACK;
    prep_repack_kernel<<<(NTOT + 255) / 256, 256>>>(x, b_in, b_f, w_in, w_f, w_out);

    // fused conv_in+conv_f -> NHWC g_conv1
    conv3x3_mma_kernel<<<dim3(15, 30, 3), 256, SMEM_BYTES>>>(p_xh, p_xl, p_wrep,
                                                             p_bias, p_conv1, 288, 1);

    attn_winrow_kernel<<<1920 + 4608, 256>>>(ls, lr_ls);
    axial_col_kernel<<<8 * IMGW, 128>>>(lr_ls);

    unsigned* wrep_out = p_wrep + 2 * 288 * 432;
    // conv_out -> planar harness output
    conv3x3_mma_kernel<<<dim3(15, 30, 1), 256, SMEM_BYTES>>>(p_yh, p_yl, wrep_out,
                                                             b_out, out, 96, 0);
}

// round 16
// speedup vs baseline: 1.2471x; 1.0001x over previous
#include <cuda_runtime.h>
#include <cuda_bf16.h>
#include <math.h>

#define HW    57600
#define IMGW  240
#define PW    244
#define PH    242
#define PHW   (PH * PW)      // 59048
#define LOG_MAX 4.6051701859880914f
#define LOG2E   1.4426950408889634f

// Scratch (allocation-free):
__device__ float    g_conv1[288 * HW];     // NHWC: [pos][ch], stride 288
__device__ float    g_v1[32 * HW];         // NHWC: [pos][ch], stride 32
__device__ unsigned g_wrep[768 * 864];
__device__ float    g_bias[288];
__device__ unsigned g_xa_hi[48 * PHW];
__device__ unsigned g_xa_lo[48 * PHW];
__device__ unsigned g_ya_hi[48 * PHW];
__device__ unsigned g_ya_lo[48 * PHW];

__device__ __forceinline__ unsigned pack_bf2(float a, float b) {
    __nv_bfloat162 h;
    h.x = __float2bfloat16_rn(a);
    h.y = __float2bfloat16_rn(b);
    return *(unsigned*)&h;
}
__device__ __forceinline__ unsigned smem_u32(const void* p) {
    return (unsigned)__cvta_generic_to_shared(p);
}
#define CP16(dst, src) asm volatile("cp.async.cg.shared.global [%0], [%1], 16;" :: "r"(dst), "l"(src))
#define CP8(dst, src)  asm volatile("cp.async.ca.shared.global [%0], [%1], 8;"  :: "r"(dst), "l"(src))
#define CP_COMMIT()    asm volatile("cp.async.commit_group;" ::: "memory")
#define CP_WAIT2()     asm volatile("cp.async.wait_group 2;" ::: "memory")

// ---- packed f32x2 helpers ----
__device__ __forceinline__ unsigned long long mul2(unsigned long long a,
                                                   unsigned long long b) {
    unsigned long long d;
    asm("mul.rn.f32x2 %0, %1, %2;" : "=l"(d) : "l"(a), "l"(b));
    return d;
}
__device__ __forceinline__ unsigned long long fma2(unsigned long long a,
                                                   unsigned long long b,
                                                   unsigned long long c) {
    unsigned long long d;
    asm("fma.rn.f32x2 %0, %1, %2, %3;" : "=l"(d) : "l"(a), "l"(b), "l"(c));
    return d;
}
__device__ __forceinline__ unsigned long long pk2(float lo, float hi) {
    unsigned long long r;
    asm("mov.b64 %0, {%1,%2};" : "=l"(r) : "f"(lo), "f"(hi));
    return r;
}
__device__ __forceinline__ float2 upk2(unsigned long long v) {
    float2 f;
    asm("mov.b64 {%0,%1}, %2;" : "=f"(f.x), "=f"(f.y) : "l"(v));
    return f;
}
// exp2 via MUFU.EX2 directly (log2e folded into q prescale).
__device__ __forceinline__ float ex2(float x) {
    float r;
    asm("ex2.approx.f32 %0, %1;" : "=f"(r) : "f"(x));
    return r;
}

// ---------------------------------------------------------------------------
// Fused prep + weight repack in ONE launch.
// ---------------------------------------------------------------------------
#define NPREP_X (48 * PHW)
#define NPREP_B (48 * (2 * PW + 4 * 240))
#define NREPACK (384 * 432)

__device__ __forceinline__ void repack_one(const float* wt, unsigned* wrep,
                                           int idx, int CoutLocal, int ocOff,
                                           int CoutTotal) {
    int o = idx % CoutLocal;
    int rem = idx / CoutLocal;
    int p = rem % 8; int rem2 = rem / 8;
    int s = rem2 % 9;
    int ch = rem2 / 9;
    int ic = ch * 16 + 2 * p;
    float v0 = wt[(o * 96 + ic) * 9 + s];
    float v1 = wt[(o * 96 + ic + 1) * 9 + s];
    __nv_bfloat16 h0 = __float2bfloat16_rn(v0);
    __nv_bfloat16 h1 = __float2bfloat16_rn(v1);
    __nv_bfloat162 hi; hi.x = h0; hi.y = h1;
    int dst = rem * CoutTotal + ocOff + o;
    wrep[dst] = *(unsigned*)&hi;
    wrep[CoutTotal * 432 + dst] =
        pack_bf2(v0 - __bfloat162float(h0), v1 - __bfloat162float(h1));
}

__global__ void prep_repack_kernel(const float* __restrict__ x,
                                   const float* __restrict__ b_in,
                                   const float* __restrict__ b_f,
                                   const float* __restrict__ w_in,
                                   const float* __restrict__ w_f,
                                   const float* __restrict__ w_out) {
    int idx = blockIdx.x * 256 + threadIdx.x;
    if (idx < NPREP_X) {
        int p = idx / PHW, rem = idx % PHW;
        int py = rem / PW, px = rem % PW;
        float v0 = 0.f, v1 = 0.f;
        if (py >= 1 && py <= 240 && px >= 1 && px <= 240) {
            int pos = (py - 1) * IMGW + (px - 1);
            v0 = x[(2 * p) * HW + pos];
            v1 = x[(2 * p + 1) * HW + pos];
        }
        __nv_bfloat16 h0 = __float2bfloat16_rn(v0);
        __nv_bfloat16 h1 = __float2bfloat16_rn(v1);
        __nv_bfloat162 hh; hh.x = h0; hh.y = h1;
        g_xa_hi[idx] = *(unsigned*)&hh;
        g_xa_lo[idx] = pack_bf2(v0 - __bfloat162float(h0), v1 - __bfloat162float(h1));
        return;
    }
    idx -= NPREP_X;
    if (idx < NPREP_B) {
        const int PER = 2 * PW + 4 * 240;
        int p = idx / PER, j = idx % PER;
        int py, px;
        if (j < 2 * PW) { py = (j / PW) ? 241 : 0; px = j % PW; }
        else {
            int k = j - 2 * PW;
            py = 1 + (k % 240);
            int c = k / 240;
            px = (c == 0) ? 0 : 240 + c;
        }
        int o = p * PHW + py * PW + px;
        g_ya_hi[o] = 0u;
        g_ya_lo[o] = 0u;
        return;
    }
    idx -= NPREP_B;
    if (idx < 288) {
        g_bias[idx] = idx < 192 ? b_in[idx] : b_f[idx - 192];
        return;
    }
    idx -= 288;
    const int T1 = 192 * 432, T2 = 96 * 432;
    if (idx < T1) { repack_one(w_in, g_wrep, idx, 192, 0, 288); return; }
    idx -= T1;
    if (idx < T2) { repack_one(w_f, g_wrep, idx, 96, 192, 288); return; }
    idx -= T2;
    if (idx < T2) repack_one(w_out, g_wrep + 2 * 288 * 432, idx, 96, 0, 96);
}

// ---------------------------------------------------------------------------
// Implicit-GEMM 3x3 conv (best-known pipeline). out_nhwc: 0 = planar
// (oc*HW+pos, final output), 1 = NHWC pos*288+oc (g_conv1).
// ---------------------------------------------------------------------------
__global__ __launch_bounds__(256, 2) void conv3x3_mma_kernel(
    const unsigned* __restrict__ in_hi, const unsigned* __restrict__ in_lo,
    const unsigned* __restrict__ wrep, const float* __restrict__ bias,
    float* __restrict__ out, int Cout, int out_nhwc) {
    extern __shared__ unsigned smem[];
    unsigned* s_b_hi = smem + 6400;
    unsigned* s_b_lo = smem + 13312;

    const int tid = threadIdx.x;
    const int lane = tid & 31, w = tid >> 5;
    const int wm = w & 1, wn = w >> 1;
    const int x0 = blockIdx.x * 16, y0 = blockIdx.y * 8;
    const int oc_blk = blockIdx.z * 96;
    const int g = lane >> 2, t = lane & 3;
    const int wlo = Cout * 432;

    auto stage_a = [&](int ch, int buf) {
        unsigned* a_base = smem + buf * 3200;
        for (int i = tid; i < 800; i += 256) {
            int p = i / 100, r = i % 100;
            int ly = r / 10, seg = r % 10;
            int is_lo = seg >= 5, s5 = seg - is_lo * 5;
            int lx = s5 * 4;
            const unsigned* src = (is_lo ? in_lo : in_hi) +
                                  (ch * 8 + p) * PHW + (y0 + ly) * PW + x0 + lx;
            unsigned dst = smem_u32(a_base + is_lo * 1600 + p * 200 + ly * 20 + lx);
            if (s5 < 4) CP16(dst, src);
            else        CP8(dst, src);
        }
    };
    auto stage_b_rows = [&](int ch, int r0, int nrows) {
        int half = nrows * 24;
        for (int i = tid; i < half * 2; i += 256) {
            int is_lo = i >= half, k = i - is_lo * half;
            int r = r0 + k / 24, c = k % 24;
            const unsigned* src = wrep + is_lo * wlo +
                                  (ch * 72 + r) * Cout + oc_blk + c * 4;
            int col = (c * 4) ^ ((r & 3) * 8);
            unsigned dst = smem_u32((is_lo ? s_b_lo : s_b_hi) + r * 96 + col);
            CP16(dst, src);
        }
    };

    float acc[4][3][4];
#pragma unroll
    for (int j = 0; j < 3; j++) {
        int oc = oc_blk + wn * 24 + j * 8 + 2 * t;
        float b0 = bias[oc], b1 = bias[oc + 1];
#pragma unroll
        for (int i = 0; i < 4; i++) {
            acc[i][j][0] = b0; acc[i][j][1] = b1;
            acc[i][j][2] = b0; acc[i][j][3] = b1;
        }
    }

    stage_a(0, 0);           CP_COMMIT();
    stage_b_rows(0, 0, 40);  CP_COMMIT();
    stage_b_rows(0, 40, 32); CP_COMMIT();

    const unsigned* a_hi;
    const unsigned* a_lo;
    auto compute_shift = [&](int s) {
        const int dy = s / 3, dx = s % 3;
        unsigned bh[3][2], bl[3][2];
        const int swz = t * 8;
#pragma unroll
        for (int j = 0; j < 3; j++) {
            int oc = (wn * 24 + j * 8 + g) ^ swz;
            bh[j][0] = s_b_hi[(s * 8 + t) * 96 + oc];
            bh[j][1] = s_b_hi[(s * 8 + t + 4) * 96 + oc];
            bl[j][0] = s_b_lo[(s * 8 + t) * 96 + oc];
            bl[j][1] = s_b_lo[(s * 8 + t + 4) * 96 + oc];
        }
#pragma unroll
        for (int i = 0; i < 4; i++) {
            int py = wm * 4 + i;
            int o00 = t * 200 + (py + dy) * 20 + g + dx;
            int o4  = o00 + 800;
            unsigned ah0 = a_hi[o00], ah1 = a_hi[o00 + 8];
            unsigned ah2 = a_hi[o4],  ah3 = a_hi[o4 + 8];
            unsigned al0 = a_lo[o00], al1 = a_lo[o00 + 8];
            unsigned al2 = a_lo[o4],  al3 = a_lo[o4 + 8];
#pragma unroll
            for (int j = 0; j < 3; j++) {
                asm volatile(
                    "mma.sync.aligned.m16n8k16.row.col.f32.bf16.bf16.f32 "
                    "{%0,%1,%2,%3}, {%4,%5,%6,%7}, {%8,%9}, {%0,%1,%2,%3};"
                    : "+f"(acc[i][j][0]), "+f"(acc[i][j][1]),
                      "+f"(acc[i][j][2]), "+f"(acc[i][j][3])
                    : "r"(al0), "r"(al1), "r"(al2), "r"(al3),
                      "r"(bh[j][0]), "r"(bh[j][1]));
                asm volatile(
                    "mma.sync.aligned.m16n8k16.row.col.f32.bf16.bf16.f32 "
                    "{%0,%1,%2,%3}, {%4,%5,%6,%7}, {%8,%9}, {%0,%1,%2,%3};"
                    : "+f"(acc[i][j][0]), "+f"(acc[i][j][1]),
                      "+f"(acc[i][j][2]), "+f"(acc[i][j][3])
                    : "r"(ah0), "r"(ah1), "r"(ah2), "r"(ah3),
                      "r"(bl[j][0]), "r"(bl[j][1]));
                asm volatile(
                    "mma.sync.aligned.m16n8k16.row.col.f32.bf16.bf16.f32 "
                    "{%0,%1,%2,%3}, {%4,%5,%6,%7}, {%8,%9}, {%0,%1,%2,%3};"
                    : "+f"(acc[i][j][0]), "+f"(acc[i][j][1]),
                      "+f"(acc[i][j][2]), "+f"(acc[i][j][3])
                    : "r"(ah0), "r"(ah1), "r"(ah2), "r"(ah3),
                      "r"(bh[j][0]), "r"(bh[j][1]));
            }
        }
    };

    for (int ch = 0; ch < 6; ch++) {
        if (ch < 5) stage_a(ch + 1, (ch + 1) & 1);
        CP_COMMIT();
        CP_WAIT2();
        __syncthreads();

        a_hi = smem + (ch & 1) * 3200;
        a_lo = a_hi + 1600;
#pragma unroll
        for (int s = 0; s < 5; s++) compute_shift(s);
        __syncthreads();

        if (ch < 5) stage_b_rows(ch + 1, 0, 40);
        CP_COMMIT();
        CP_WAIT2();
        __syncthreads();
#pragma unroll
        for (int s = 5; s < 9; s++) compute_shift(s);
        __syncthreads();

        if (ch < 5) stage_b_rows(ch + 1, 40, 32);
        CP_COMMIT();
    }

    const int gx0 = x0 + g;
    if (out_nhwc) {
#pragma unroll
        for (int i = 0; i < 4; i++) {
            int gy = y0 + wm * 4 + i;
            float* r0 = out + (gy * IMGW + gx0) * 288;
            float* r8 = r0 + 8 * 288;
#pragma unroll
            for (int j = 0; j < 3; j++) {
                int oc = oc_blk + wn * 24 + j * 8 + 2 * t;
                *(float2*)(r0 + oc) = make_float2(acc[i][j][0], acc[i][j][1]);
                *(float2*)(r8 + oc) = make_float2(acc[i][j][2], acc[i][j][3]);
            }
        }
    } else {
#pragma unroll
        for (int i = 0; i < 4; i++) {
            int gy = y0 + wm * 4 + i;
#pragma unroll
            for (int j = 0; j < 3; j++) {
                int oc = oc_blk + wn * 24 + j * 8 + 2 * t;
                out[oc * HW + gy * IMGW + gx0] = acc[i][j][0];
                out[(oc + 1) * HW + gy * IMGW + gx0] = acc[i][j][1];
                out[oc * HW + gy * IMGW + gx0 + 8] = acc[i][j][2];
                out[(oc + 1) * HW + gy * IMGW + gx0 + 8] = acc[i][j][3];
            }
        }
    }
}

// l2norm via rsqrt: x * rsqrt(max(||x||^2, 1e-24)) == x / max(||x||, 1e-12).
__device__ __forceinline__ float4 l2n(float4 a) {
    float nsq = a.x * a.x + a.y * a.y + a.z * a.z + a.w * a.w;
    float inv = rsqrtf(fmaxf(nsq, 1e-24f));
    a.x *= inv; a.y *= inv; a.z *= inv; a.w *= inv;
    return a;
}

__device__ __forceinline__ void store_y_pair(int pair, int ppos, float a, float b) {
    __nv_bfloat16 ha = __float2bfloat16_rn(a), hb = __float2bfloat16_rn(b);
    __nv_bfloat162 hh; hh.x = ha; hh.y = hb;
    g_ya_hi[pair * PHW + ppos] = *(unsigned*)&hh;
    g_ya_lo[pair * PHW + ppos] =
        pack_bf2(a - __bfloat162float(ha), b - __bfloat162float(hb));
}

// NHWC q fetch, normalized and prescaled by sc*log2e (for ex2-based softmax).
__device__ __forceinline__ void load_q(int n, int pos, float sc2,
                                       unsigned long long& qxy,
                                       unsigned long long& qzw) {
    float4 q = *(const float4*)(g_conv1 + pos * 288 + 256 + n * 4);
    q = l2n(q);
    qxy = pk2(q.x * sc2, q.y * sc2);
    qzw = pk2(q.z * sc2, q.w * sc2);
}

// ---------------------------------------------------------------------------
// Attention launch #1: heavy axial ROW blocks (bx<1920, 2 q/thread) first,
// then WINDOW blocks. exp2-based softmax (log2e folded into q prescale).
// ---------------------------------------------------------------------------
__global__ __launch_bounds__(256) void attn_winrow_kernel(
    const float* __restrict__ ls, const float* __restrict__ lrls) {
    __shared__ ulonglong2 s_k2[240];
    __shared__ ulonglong2 s_v2[240];
    __shared__ float s_sc[8];
    const int bx = blockIdx.x;
    const int t = threadIdx.x;

    if (bx >= 1920) {
        // ---- window attention ----
        const int wb = bx - 1920;
        const int branch = wb / 2304;
        const int win = wb - branch * 2304;
        const int Hw = win / 48, Ww = win % 48;
        if (t < 8) s_sc[t] = expf(fminf(ls[t], LOG_MAX)) * LOG2E;

        const int n = t / 25, tok = t % 25;
        const int wy = tok / 5, wx = tok % 5;
        const int py = Hw * 5 + wy, px = Ww * 5 + wx;
        int gy = py, gx = px;
        if (branch) { gy = (gy + 3) % IMGW; gx = (gx + 3) % IMGW; }
        const int pos = gy * IMGW + gx;

        if (t < 200) {
            const float* base = g_conv1 + pos * 288 + branch * 64 + n * 4;
            float4 kk = *(const float4*)base;
            float4 vv = *(const float4*)(base + 32);
            kk = l2n(kk);
            s_k2[n * 25 + tok] = make_ulonglong2(pk2(kk.x, kk.y), pk2(kk.z, kk.w));
            s_v2[n * 25 + tok] = make_ulonglong2(pk2(vv.x, vv.y), pk2(vv.z, vv.w));
        }
        __syncthreads();
        if (t >= 200) return;

        float4 q = *(const float4*)(g_conv1 + pos * 288 + 192 + branch * 32 + n * 4);
        q = l2n(q);
        const float sc2 = s_sc[n];
        const unsigned long long qxy = pk2(q.x * sc2, q.y * sc2);
        const unsigned long long qzw = pk2(q.z * sc2, q.w * sc2);

        float l = 0.f;
        unsigned long long axy = 0ull, azw = 0ull;
#pragma unroll
        for (int j = 0; j < 25; j++) {
            ulonglong2 kj = s_k2[n * 25 + j];
            ulonglong2 vj = s_v2[n * 25 + j];
            float2 ss = upk2(fma2(qzw, kj.y, mul2(qxy, kj.x)));
            float wgt = ex2(ss.x + ss.y);
            unsigned long long ww = pk2(wgt, wgt);
            axy = fma2(ww, vj.x, axy);
            azw = fma2(ww, vj.y, azw);
            l += wgt;
        }
        float invl = 1.f / l;
        float2 a01 = upk2(axy), a23 = upk2(azw);

        int oy = py, ox = px;
        if (branch) { oy = (oy + 2) % IMGW; ox = (ox + 2) % IMGW; }
        const int ppos = (oy + 1) * PW + (ox + 1);
        const int pair0 = branch * 16 + 2 * n;
        store_y_pair(pair0,     ppos, a01.x * invl, a01.y * invl);
        store_y_pair(pair0 + 1, ppos, a23.x * invl, a23.y * invl);
        return;
    }

    // ---- axial row attention: 2 queries/thread ----
    const int n = bx / IMGW, h = bx % IMGW;
    if (t == 0) s_sc[0] = expf(fminf(lrls[n], LOG_MAX)) * LOG2E;

    if (t < 240) {
        const int pos = h * IMGW + t;
        const float* base = g_conv1 + pos * 288 + 128 + n * 4;
        float4 kk = *(const float4*)base;
        float4 vv = *(const float4*)(base + 32);
        kk = l2n(kk);
        s_k2[t] = make_ulonglong2(pk2(kk.x, kk.y), pk2(kk.z, kk.w));
        s_v2[t] = make_ulonglong2(pk2(vv.x, vv.y), pk2(vv.z, vv.w));
    }
    __syncthreads();
    if (t >= 120) return;

    const float sc2 = s_sc[0];
    const int posA = h * IMGW + t, posB = posA + 120;
    unsigned long long qxyA, qzwA, qxyB, qzwB;
    load_q(n, posA, sc2, qxyA, qzwA);
    load_q(n, posB, sc2, qxyB, qzwB);

    float lA = 0.f, lB = 0.f;
    unsigned long long axyA = 0ull, azwA = 0ull, axyB = 0ull, azwB = 0ull;
#pragma unroll 2
    for (int j = 0; j < 240; j++) {
        ulonglong2 kj = s_k2[j];
        ulonglong2 vj = s_v2[j];
        float2 sA = upk2(fma2(qzwA, kj.y, mul2(qxyA, kj.x)));
        float2 sB = upk2(fma2(qzwB, kj.y, mul2(qxyB, kj.x)));
        float wA = ex2(sA.x + sA.y);
        float wB = ex2(sB.x + sB.y);
        unsigned long long wwA = pk2(wA, wA);
        unsigned long long wwB = pk2(wB, wB);
        axyA = fma2(wwA, vj.x, axyA);
        azwA = fma2(wwA, vj.y, azwA);
        axyB = fma2(wwB, vj.x, axyB);
        azwB = fma2(wwB, vj.y, azwB);
        lA += wA;
        lB += wB;
    }
    float iA = 1.f / lA, iB = 1.f / lB;
    float2 a01A = upk2(axyA), a23A = upk2(azwA);
    float2 a01B = upk2(axyB), a23B = upk2(azwB);
    *(float4*)(g_v1 + posA * 32 + n * 4) =
        make_float4(a01A.x * iA, a01A.y * iA, a23A.x * iA, a23A.y * iA);
    *(float4*)(g_v1 + posB * 32 + n * 4) =
        make_float4(a01B.x * iB, a01B.y * iB, a23B.x * iB, a23B.y * iB);
}

// ---------------------------------------------------------------------------
// Axial column attention: 2 queries/thread, 128-thread blocks.
// ---------------------------------------------------------------------------
__global__ __launch_bounds__(128) void axial_col_kernel(const float* __restrict__ lrls) {
    const int n = blockIdx.x / IMGW, w = blockIdx.x % IMGW;
    const int t = threadIdx.x;
    __shared__ ulonglong2 s_k2[240];
    __shared__ ulonglong2 s_v2[240];
    __shared__ float s_sc;
    if (t == 0) s_sc = expf(fminf(lrls[n], LOG_MAX)) * LOG2E;

    for (int i = t; i < 240; i += 128) {
        const int pos = i * IMGW + w;
        float4 kk = *(const float4*)(g_conv1 + pos * 288 + 128 + n * 4);
        float4 vv = *(const float4*)(g_v1 + pos * 32 + n * 4);
        kk = l2n(kk);
        s_k2[i] = make_ulonglong2(pk2(kk.x, kk.y), pk2(kk.z, kk.w));
        s_v2[i] = make_ulonglong2(pk2(vv.x, vv.y), pk2(vv.z, vv.w));
    }
    __syncthreads();
    if (t >= 120) return;

    const float sc2 = s_sc;
    const int posA = t * IMGW + w, posB = (t + 120) * IMGW + w;
    unsigned long long qxyA, qzwA, qxyB, qzwB;
    load_q(n, posA, sc2, qxyA, qzwA);
    load_q(n, posB, sc2, qxyB, qzwB);

    float lA = 0.f, lB = 0.f;
    unsigned long long axyA = 0ull, azwA = 0ull, axyB = 0ull, azwB = 0ull;
#pragma unroll 2
    for (int j = 0; j < 240; j++) {
        ulonglong2 kj = s_k2[j];
        ulonglong2 vj = s_v2[j];
        float2 sA = upk2(fma2(qzwA, kj.y, mul2(qxyA, kj.x)));
        float2 sB = upk2(fma2(qzwB, kj.y, mul2(qxyB, kj.x)));
        float wA = ex2(sA.x + sA.y);
        float wB = ex2(sB.x + sB.y);
        unsigned long long wwA = pk2(wA, wA);
        unsigned long long wwB = pk2(wB, wB);
        axyA = fma2(wwA, vj.x, axyA);
        azwA = fma2(wwA, vj.y, azwA);
        axyB = fma2(wwB, vj.x, axyB);
        azwB = fma2(wwB, vj.y, azwB);
        lA += wA;
        lB += wB;
    }
    float iA = 1.f / lA, iB = 1.f / lB;
    float2 a01A = upk2(axyA), a23A = upk2(azwA);
    float2 a01B = upk2(axyB), a23B = upk2(azwB);
    const int pair0 = 32 + 2 * n;
    const int pposA = (t + 1) * PW + (w + 1);
    const int pposB = (t + 121) * PW + (w + 1);
    store_y_pair(pair0,     pposA, a01A.x * iA, a01A.y * iA);
    store_y_pair(pair0 + 1, pposA, a23A.x * iA, a23A.y * iA);
    store_y_pair(pair0,     pposB, a01B.x * iB, a01B.y * iB);
    store_y_pair(pair0 + 1, pposB, a23B.x * iB, a23B.y * iB);
}

// ---------------------------------------------------------------------------
extern "C" void kernel_launch(void* const* d_in, const int* in_sizes, int n_in,
                              void* d_out, int out_size) {
    const float* x      = (const float*)d_in[0];
    const float* w_in   = (const float*)d_in[1];
    const float* b_in   = (const float*)d_in[2];
    const float* w_f    = (const float*)d_in[3];
    const float* b_f    = (const float*)d_in[4];
    const float* w_out  = (const float*)d_in[5];
    const float* b_out  = (const float*)d_in[6];
    const float* ls     = (const float*)d_in[7];
    const float* lr_ls  = (const float*)d_in[8];
    float* out = (float*)d_out;

    float* p_conv1; unsigned* p_wrep; float* p_bias;
    unsigned *p_xh, *p_xl, *p_yh, *p_yl;
    cudaGetSymbolAddress((void**)&p_conv1, g_conv1);
    cudaGetSymbolAddress((void**)&p_wrep, g_wrep);
    cudaGetSymbolAddress((void**)&p_bias, g_bias);
    cudaGetSymbolAddress((void**)&p_xh, g_xa_hi);
    cudaGetSymbolAddress((void**)&p_xl, g_xa_lo);
    cudaGetSymbolAddress((void**)&p_yh, g_ya_hi);
    cudaGetSymbolAddress((void**)&p_yl, g_ya_lo);

    const int SMEM_BYTES = 20224 * 4;
    static int attr_set = 0;
    if (!attr_set) {
        cudaFuncSetAttribute(conv3x3_mma_kernel,
                             cudaFuncAttributeMaxDynamicSharedMemorySize, SMEM_BYTES);
        attr_set = 1;
    }

    const int NTOT = NPREP_X + NPREP_B + 288 + NREPACK;
    prep_repack_kernel<<<(NTOT + 255) / 256, 256>>>(x, b_in, b_f, w_in, w_f, w_out);

    // fused conv_in+conv_f -> NHWC g_conv1
    conv3x3_mma_kernel<<<dim3(15, 30, 3), 256, SMEM_BYTES>>>(p_xh, p_xl, p_wrep,
                                                             p_bias, p_conv1, 288, 1);

    attn_winrow_kernel<<<1920 + 4608, 256>>>(ls, lr_ls);
    axial_col_kernel<<<8 * IMGW, 128>>>(lr_ls);

    unsigned* wrep_out = p_wrep + 2 * 288 * 432;
    // conv_out -> planar harness output
    conv3x3_mma_kernel<<<dim3(15, 30, 1), 256, SMEM_BYTES>>>(p_yh, p_yl, wrep_out,
                                                             b_out, out, 96, 0);
}

// round 17
// speedup vs baseline: 1.2639x; 1.0135x over previous
#include <cuda_runtime.h>
#include <cuda_bf16.h>
#include <math.h>

#define HW    57600
#define IMGW  240
#define PW    244
#define PH    242
#define PHW   (PH * PW)      // 59048
#define LOG_MAX 4.6051701859880914f
#define LOG2E   1.4426950408889634f

// Scratch (allocation-free):
__device__ float    g_conv1[288 * HW];     // NHWC: [pos][ch], stride 288
__device__ float    g_v1[32 * HW];         // NHWC: [pos][ch], stride 32
__device__ unsigned g_wrep[768 * 864];
__device__ float    g_bias[288];
__device__ unsigned g_xa_hi[48 * PHW];
__device__ unsigned g_xa_lo[48 * PHW];
__device__ unsigned g_ya_hi[48 * PHW];
__device__ unsigned g_ya_lo[48 * PHW];

__device__ __forceinline__ unsigned pack_bf2(float a, float b) {
    __nv_bfloat162 h;
    h.x = __float2bfloat16_rn(a);
    h.y = __float2bfloat16_rn(b);
    return *(unsigned*)&h;
}
__device__ __forceinline__ unsigned smem_u32(const void* p) {
    return (unsigned)__cvta_generic_to_shared(p);
}
#define CP16(dst, src) asm volatile("cp.async.cg.shared.global [%0], [%1], 16;" :: "r"(dst), "l"(src))
#define CP8(dst, src)  asm volatile("cp.async.ca.shared.global [%0], [%1], 8;"  :: "r"(dst), "l"(src))
#define CP_COMMIT()    asm volatile("cp.async.commit_group;" ::: "memory")
#define CP_WAIT2()     asm volatile("cp.async.wait_group 2;" ::: "memory")

// ---- packed f32x2 helpers ----
__device__ __forceinline__ unsigned long long mul2(unsigned long long a,
                                                   unsigned long long b) {
    unsigned long long d;
    asm("mul.rn.f32x2 %0, %1, %2;" : "=l"(d) : "l"(a), "l"(b));
    return d;
}
__device__ __forceinline__ unsigned long long fma2(unsigned long long a,
                                                   unsigned long long b,
                                                   unsigned long long c) {
    unsigned long long d;
    asm("fma.rn.f32x2 %0, %1, %2, %3;" : "=l"(d) : "l"(a), "l"(b), "l"(c));
    return d;
}
__device__ __forceinline__ unsigned long long pk2(float lo, float hi) {
    unsigned long long r;
    asm("mov.b64 %0, {%1,%2};" : "=l"(r) : "f"(lo), "f"(hi));
    return r;
}
__device__ __forceinline__ float2 upk2(unsigned long long v) {
    float2 f;
    asm("mov.b64 {%0,%1}, %2;" : "=f"(f.x), "=f"(f.y) : "l"(v));
    return f;
}
__device__ __forceinline__ float ex2(float x) {
    float r;
    asm("ex2.approx.f32 %0, %1;" : "=f"(r) : "f"(x));
    return r;
}

// ---------------------------------------------------------------------------
// Fused prep + weight repack in ONE launch.
// ---------------------------------------------------------------------------
#define NPREP_X (48 * PHW)
#define NPREP_B (48 * (2 * PW + 4 * 240))
#define NREPACK (384 * 432)

__device__ __forceinline__ void repack_one(const float* wt, unsigned* wrep,
                                           int idx, int CoutLocal, int ocOff,
                                           int CoutTotal) {
    int o = idx % CoutLocal;
    int rem = idx / CoutLocal;
    int p = rem % 8; int rem2 = rem / 8;
    int s = rem2 % 9;
    int ch = rem2 / 9;
    int ic = ch * 16 + 2 * p;
    float v0 = wt[(o * 96 + ic) * 9 + s];
    float v1 = wt[(o * 96 + ic + 1) * 9 + s];
    __nv_bfloat16 h0 = __float2bfloat16_rn(v0);
    __nv_bfloat16 h1 = __float2bfloat16_rn(v1);
    __nv_bfloat162 hi; hi.x = h0; hi.y = h1;
    int dst = rem * CoutTotal + ocOff + o;
    wrep[dst] = *(unsigned*)&hi;
    wrep[CoutTotal * 432 + dst] =
        pack_bf2(v0 - __bfloat162float(h0), v1 - __bfloat162float(h1));
}

__global__ void prep_repack_kernel(const float* __restrict__ x,
                                   const float* __restrict__ b_in,
                                   const float* __restrict__ b_f,
                                   const float* __restrict__ w_in,
                                   const float* __restrict__ w_f,
                                   const float* __restrict__ w_out) {
    int idx = blockIdx.x * 256 + threadIdx.x;
    if (idx < NPREP_X) {
        int p = idx / PHW, rem = idx % PHW;
        int py = rem / PW, px = rem % PW;
        float v0 = 0.f, v1 = 0.f;
        if (py >= 1 && py <= 240 && px >= 1 && px <= 240) {
            int pos = (py - 1) * IMGW + (px - 1);
            v0 = x[(2 * p) * HW + pos];
            v1 = x[(2 * p + 1) * HW + pos];
        }
        __nv_bfloat16 h0 = __float2bfloat16_rn(v0);
        __nv_bfloat16 h1 = __float2bfloat16_rn(v1);
        __nv_bfloat162 hh; hh.x = h0; hh.y = h1;
        g_xa_hi[idx] = *(unsigned*)&hh;
        g_xa_lo[idx] = pack_bf2(v0 - __bfloat162float(h0), v1 - __bfloat162float(h1));
        return;
    }
    idx -= NPREP_X;
    if (idx < NPREP_B) {
        const int PER = 2 * PW + 4 * 240;
        int p = idx / PER, j = idx % PER;
        int py, px;
        if (j < 2 * PW) { py = (j / PW) ? 241 : 0; px = j % PW; }
        else {
            int k = j - 2 * PW;
            py = 1 + (k % 240);
            int c = k / 240;
            px = (c == 0) ? 0 : 240 + c;
        }
        int o = p * PHW + py * PW + px;
        g_ya_hi[o] = 0u;
        g_ya_lo[o] = 0u;
        return;
    }
    idx -= NPREP_B;
    if (idx < 288) {
        g_bias[idx] = idx < 192 ? b_in[idx] : b_f[idx - 192];
        return;
    }
    idx -= 288;
    const int T1 = 192 * 432, T2 = 96 * 432;
    if (idx < T1) { repack_one(w_in, g_wrep, idx, 192, 0, 288); return; }
    idx -= T1;
    if (idx < T2) { repack_one(w_f, g_wrep, idx, 96, 192, 288); return; }
    idx -= T2;
    if (idx < T2) repack_one(w_out, g_wrep + 2 * 288 * 432, idx, 96, 0, 96);
}

// ---------------------------------------------------------------------------
// Implicit-GEMM 3x3 conv (best-known pipeline). out_nhwc: 0 = planar,
// 1 = NHWC pos*288+oc.
// ---------------------------------------------------------------------------
__global__ __launch_bounds__(256, 2) void conv3x3_mma_kernel(
    const unsigned* __restrict__ in_hi, const unsigned* __restrict__ in_lo,
    const unsigned* __restrict__ wrep, const float* __restrict__ bias,
    float* __restrict__ out, int Cout, int out_nhwc) {
    extern __shared__ unsigned smem[];
    unsigned* s_b_hi = smem + 6400;
    unsigned* s_b_lo = smem + 13312;

    const int tid = threadIdx.x;
    const int lane = tid & 31, w = tid >> 5;
    const int wm = w & 1, wn = w >> 1;
    const int x0 = blockIdx.x * 16, y0 = blockIdx.y * 8;
    const int oc_blk = blockIdx.z * 96;
    const int g = lane >> 2, t = lane & 3;
    const int wlo = Cout * 432;

    auto stage_a = [&](int ch, int buf) {
        unsigned* a_base = smem + buf * 3200;
        for (int i = tid; i < 800; i += 256) {
            int p = i / 100, r = i % 100;
            int ly = r / 10, seg = r % 10;
            int is_lo = seg >= 5, s5 = seg - is_lo * 5;
            int lx = s5 * 4;
            const unsigned* src = (is_lo ? in_lo : in_hi) +
                                  (ch * 8 + p) * PHW + (y0 + ly) * PW + x0 + lx;
            unsigned dst = smem_u32(a_base + is_lo * 1600 + p * 200 + ly * 20 + lx);
            if (s5 < 4) CP16(dst, src);
            else        CP8(dst, src);
        }
    };
    auto stage_b_rows = [&](int ch, int r0, int nrows) {
        int half = nrows * 24;
        for (int i = tid; i < half * 2; i += 256) {
            int is_lo = i >= half, k = i - is_lo * half;
            int r = r0 + k / 24, c = k % 24;
            const unsigned* src = wrep + is_lo * wlo +
                                  (ch * 72 + r) * Cout + oc_blk + c * 4;
            int col = (c * 4) ^ ((r & 3) * 8);
            unsigned dst = smem_u32((is_lo ? s_b_lo : s_b_hi) + r * 96 + col);
            CP16(dst, src);
        }
    };

    float acc[4][3][4];
#pragma unroll
    for (int j = 0; j < 3; j++) {
        int oc = oc_blk + wn * 24 + j * 8 + 2 * t;
        float b0 = bias[oc], b1 = bias[oc + 1];
#pragma unroll
        for (int i = 0; i < 4; i++) {
            acc[i][j][0] = b0; acc[i][j][1] = b1;
            acc[i][j][2] = b0; acc[i][j][3] = b1;
        }
    }

    stage_a(0, 0);           CP_COMMIT();
    stage_b_rows(0, 0, 40);  CP_COMMIT();
    stage_b_rows(0, 40, 32); CP_COMMIT();

    const unsigned* a_hi;
    const unsigned* a_lo;
    auto compute_shift = [&](int s) {
        const int dy = s / 3, dx = s % 3;
        unsigned bh[3][2], bl[3][2];
        const int swz = t * 8;
#pragma unroll
        for (int j = 0; j < 3; j++) {
            int oc = (wn * 24 + j * 8 + g) ^ swz;
            bh[j][0] = s_b_hi[(s * 8 + t) * 96 + oc];
            bh[j][1] = s_b_hi[(s * 8 + t + 4) * 96 + oc];
            bl[j][0] = s_b_lo[(s * 8 + t) * 96 + oc];
            bl[j][1] = s_b_lo[(s * 8 + t + 4) * 96 + oc];
        }
#pragma unroll
        for (int i = 0; i < 4; i++) {
            int py = wm * 4 + i;
            int o00 = t * 200 + (py + dy) * 20 + g + dx;
            int o4  = o00 + 800;
            unsigned ah0 = a_hi[o00], ah1 = a_hi[o00 + 8];
            unsigned ah2 = a_hi[o4],  ah3 = a_hi[o4 + 8];
            unsigned al0 = a_lo[o00], al1 = a_lo[o00 + 8];
            unsigned al2 = a_lo[o4],  al3 = a_lo[o4 + 8];
#pragma unroll
            for (int j = 0; j < 3; j++) {
                asm volatile(
                    "mma.sync.aligned.m16n8k16.row.col.f32.bf16.bf16.f32 "
                    "{%0,%1,%2,%3}, {%4,%5,%6,%7}, {%8,%9}, {%0,%1,%2,%3};"
                    : "+f"(acc[i][j][0]), "+f"(acc[i][j][1]),
                      "+f"(acc[i][j][2]), "+f"(acc[i][j][3])
                    : "r"(al0), "r"(al1), "r"(al2), "r"(al3),
                      "r"(bh[j][0]), "r"(bh[j][1]));
                asm volatile(
                    "mma.sync.aligned.m16n8k16.row.col.f32.bf16.bf16.f32 "
                    "{%0,%1,%2,%3}, {%4,%5,%6,%7}, {%8,%9}, {%0,%1,%2,%3};"
                    : "+f"(acc[i][j][0]), "+f"(acc[i][j][1]),
                      "+f"(acc[i][j][2]), "+f"(acc[i][j][3])
                    : "r"(ah0), "r"(ah1), "r"(ah2), "r"(ah3),
                      "r"(bl[j][0]), "r"(bl[j][1]));
                asm volatile(
                    "mma.sync.aligned.m16n8k16.row.col.f32.bf16.bf16.f32 "
                    "{%0,%1,%2,%3}, {%4,%5,%6,%7}, {%8,%9}, {%0,%1,%2,%3};"
                    : "+f"(acc[i][j][0]), "+f"(acc[i][j][1]),
                      "+f"(acc[i][j][2]), "+f"(acc[i][j][3])
                    : "r"(ah0), "r"(ah1), "r"(ah2), "r"(ah3),
                      "r"(bh[j][0]), "r"(bh[j][1]));
            }
        }
    };

    for (int ch = 0; ch < 6; ch++) {
        if (ch < 5) stage_a(ch + 1, (ch + 1) & 1);
        CP_COMMIT();
        CP_WAIT2();
        __syncthreads();

        a_hi = smem + (ch & 1) * 3200;
        a_lo = a_hi + 1600;
#pragma unroll
        for (int s = 0; s < 5; s++) compute_shift(s);
        __syncthreads();

        if (ch < 5) stage_b_rows(ch + 1, 0, 40);
        CP_COMMIT();
        CP_WAIT2();
        __syncthreads();
#pragma unroll
        for (int s = 5; s < 9; s++) compute_shift(s);
        __syncthreads();

        if (ch < 5) stage_b_rows(ch + 1, 40, 32);
        CP_COMMIT();
    }

    const int gx0 = x0 + g;
    if (out_nhwc) {
#pragma unroll
        for (int i = 0; i < 4; i++) {
            int gy = y0 + wm * 4 + i;
            float* r0 = out + (gy * IMGW + gx0) * 288;
            float* r8 = r0 + 8 * 288;
#pragma unroll
            for (int j = 0; j < 3; j++) {
                int oc = oc_blk + wn * 24 + j * 8 + 2 * t;
                *(float2*)(r0 + oc) = make_float2(acc[i][j][0], acc[i][j][1]);
                *(float2*)(r8 + oc) = make_float2(acc[i][j][2], acc[i][j][3]);
            }
        }
    } else {
#pragma unroll
        for (int i = 0; i < 4; i++) {
            int gy = y0 + wm * 4 + i;
#pragma unroll
            for (int j = 0; j < 3; j++) {
                int oc = oc_blk + wn * 24 + j * 8 + 2 * t;
                out[oc * HW + gy * IMGW + gx0] = acc[i][j][0];
                out[(oc + 1) * HW + gy * IMGW + gx0] = acc[i][j][1];
                out[oc * HW + gy * IMGW + gx0 + 8] = acc[i][j][2];
                out[(oc + 1) * HW + gy * IMGW + gx0 + 8] = acc[i][j][3];
            }
        }
    }
}

// l2norm via rsqrt: x * rsqrt(max(||x||^2, 1e-24)) == x / max(||x||, 1e-12).
__device__ __forceinline__ float4 l2n(float4 a) {
    float nsq = a.x * a.x + a.y * a.y + a.z * a.z + a.w * a.w;
    float inv = rsqrtf(fmaxf(nsq, 1e-24f));
    a.x *= inv; a.y *= inv; a.z *= inv; a.w *= inv;
    return a;
}

__device__ __forceinline__ void store_y_pair(int pair, int ppos, float a, float b) {
    __nv_bfloat16 ha = __float2bfloat16_rn(a), hb = __float2bfloat16_rn(b);
    __nv_bfloat162 hh; hh.x = ha; hh.y = hb;
    g_ya_hi[pair * PHW + ppos] = *(unsigned*)&hh;
    g_ya_lo[pair * PHW + ppos] =
        pack_bf2(a - __bfloat162float(ha), b - __bfloat162float(hb));
}

__device__ __forceinline__ void load_q(int n, int pos, float sc2,
                                       unsigned long long& qxy,
                                       unsigned long long& qzw) {
    float4 q = *(const float4*)(g_conv1 + pos * 288 + 256 + n * 4);
    q = l2n(q);
    qxy = pk2(q.x * sc2, q.y * sc2);
    qzw = pk2(q.z * sc2, q.w * sc2);
}

// Window-attention block body (one branch, one window). 256 threads.
__device__ __forceinline__ void window_block(int branch, int win,
                                             const float* __restrict__ ls,
                                             ulonglong2* s_k2, ulonglong2* s_v2,
                                             float* s_sc) {
    const int t = threadIdx.x;
    const int Hw = win / 48, Ww = win % 48;
    if (t < 8) s_sc[t] = expf(fminf(ls[t], LOG_MAX)) * LOG2E;

    const int n = t / 25, tok = t % 25;
    const int wy = tok / 5, wx = tok % 5;
    const int py = Hw * 5 + wy, px = Ww * 5 + wx;
    int gy = py, gx = px;
    if (branch) { gy = (gy + 3) % IMGW; gx = (gx + 3) % IMGW; }
    const int pos = gy * IMGW + gx;

    if (t < 200) {
        const float* base = g_conv1 + pos * 288 + branch * 64 + n * 4;
        float4 kk = *(const float4*)base;
        float4 vv = *(const float4*)(base + 32);
        kk = l2n(kk);
        s_k2[n * 25 + tok] = make_ulonglong2(pk2(kk.x, kk.y), pk2(kk.z, kk.w));
        s_v2[n * 25 + tok] = make_ulonglong2(pk2(vv.x, vv.y), pk2(vv.z, vv.w));
    }
    __syncthreads();
    if (t >= 200) return;

    float4 q = *(const float4*)(g_conv1 + pos * 288 + 192 + branch * 32 + n * 4);
    q = l2n(q);
    const float sc2 = s_sc[n];
    const unsigned long long qxy = pk2(q.x * sc2, q.y * sc2);
    const unsigned long long qzw = pk2(q.z * sc2, q.w * sc2);

    float l = 0.f;
    unsigned long long axy = 0ull, azw = 0ull;
#pragma unroll
    for (int j = 0; j < 25; j++) {
        ulonglong2 kj = s_k2[n * 25 + j];
        ulonglong2 vj = s_v2[n * 25 + j];
        float2 ss = upk2(fma2(qzw, kj.y, mul2(qxy, kj.x)));
        float wgt = ex2(ss.x + ss.y);
        unsigned long long ww = pk2(wgt, wgt);
        axy = fma2(ww, vj.x, axy);
        azw = fma2(ww, vj.y, azw);
        l += wgt;
    }
    float invl = 1.f / l;
    float2 a01 = upk2(axy), a23 = upk2(azw);

    int oy = py, ox = px;
    if (branch) { oy = (oy + 2) % IMGW; ox = (ox + 2) % IMGW; }
    const int ppos = (oy + 1) * PW + (ox + 1);
    const int pair0 = branch * 16 + 2 * n;
    store_y_pair(pair0,     ppos, a01.x * invl, a01.y * invl);
    store_y_pair(pair0 + 1, ppos, a23.x * invl, a23.y * invl);
}

// ---------------------------------------------------------------------------
// Attention launch #1: heavy axial ROW blocks (bx<1920, 2 q/thread) first,
// then WINDOW branch-0 blocks as tail filler.
// ---------------------------------------------------------------------------
__global__ __launch_bounds__(256) void attn_row_win0_kernel(
    const float* __restrict__ ls, const float* __restrict__ lrls) {
    __shared__ ulonglong2 s_k2[240];
    __shared__ ulonglong2 s_v2[240];
    __shared__ float s_sc[8];
    const int bx = blockIdx.x;
    const int t = threadIdx.x;

    if (bx >= 1920) {
        window_block(0, bx - 1920, ls, s_k2, s_v2, s_sc);
        return;
    }

    // ---- axial row attention: 2 queries/thread ----
    const int n = bx / IMGW, h = bx % IMGW;
    if (t == 0) s_sc[0] = expf(fminf(lrls[n], LOG_MAX)) * LOG2E;

    if (t < 240) {
        const int pos = h * IMGW + t;
        const float* base = g_conv1 + pos * 288 + 128 + n * 4;
        float4 kk = *(const float4*)base;
        float4 vv = *(const float4*)(base + 32);
        kk = l2n(kk);
        s_k2[t] = make_ulonglong2(pk2(kk.x, kk.y), pk2(kk.z, kk.w));
        s_v2[t] = make_ulonglong2(pk2(vv.x, vv.y), pk2(vv.z, vv.w));
    }
    __syncthreads();
    if (t >= 120) return;

    const float sc2 = s_sc[0];
    const int posA = h * IMGW + t, posB = posA + 120;
    unsigned long long qxyA, qzwA, qxyB, qzwB;
    load_q(n, posA, sc2, qxyA, qzwA);
    load_q(n, posB, sc2, qxyB, qzwB);

    float lA = 0.f, lB = 0.f;
    unsigned long long axyA = 0ull, azwA = 0ull, axyB = 0ull, azwB = 0ull;
#pragma unroll 2
    for (int j = 0; j < 240; j++) {
        ulonglong2 kj = s_k2[j];
        ulonglong2 vj = s_v2[j];
        float2 sA = upk2(fma2(qzwA, kj.y, mul2(qxyA, kj.x)));
        float2 sB = upk2(fma2(qzwB, kj.y, mul2(qxyB, kj.x)));
        float wA = ex2(sA.x + sA.y);
        float wB = ex2(sB.x + sB.y);
        unsigned long long wwA = pk2(wA, wA);
        unsigned long long wwB = pk2(wB, wB);
        axyA = fma2(wwA, vj.x, axyA);
        azwA = fma2(wwA, vj.y, azwA);
        axyB = fma2(wwB, vj.x, axyB);
        azwB = fma2(wwB, vj.y, azwB);
        lA += wA;
        lB += wB;
    }
    float iA = 1.f / lA, iB = 1.f / lB;
    float2 a01A = upk2(axyA), a23A = upk2(azwA);
    float2 a01B = upk2(axyB), a23B = upk2(azwB);
    *(float4*)(g_v1 + posA * 32 + n * 4) =
        make_float4(a01A.x * iA, a01A.y * iA, a23A.x * iA, a23A.y * iA);
    *(float4*)(g_v1 + posB * 32 + n * 4) =
        make_float4(a01B.x * iB, a01B.y * iB, a23B.x * iB, a23B.y * iB);
}

// ---------------------------------------------------------------------------
// Attention launch #2: heavy axial COL blocks (bx<960; TWO columns per block,
// 256 threads: lanes 0-119 -> col w0, 128-247 -> col w1), then WINDOW
// branch-1 blocks as tail filler.
// ---------------------------------------------------------------------------
__global__ __launch_bounds__(256) void attn_col_win1_kernel(
    const float* __restrict__ ls, const float* __restrict__ lrls) {
    __shared__ ulonglong2 s_k2[2][240];
    __shared__ ulonglong2 s_v2[2][240];
    __shared__ float s_sc[8];
    const int bx = blockIdx.x;
    const int t = threadIdx.x;

    if (bx >= 960) {
        window_block(1, bx - 960, ls, s_k2[0], s_v2[0], s_sc);
        return;
    }

    const int n = bx / 120, wp = bx % 120;
    const int w0 = 2 * wp;
    if (t == 0) s_sc[0] = expf(fminf(lrls[n], LOG_MAX)) * LOG2E;

    for (int i = t; i < 480; i += 256) {
        int cs = i / 240, idx = i % 240;
        const int pos = idx * IMGW + w0 + cs;
        float4 kk = *(const float4*)(g_conv1 + pos * 288 + 128 + n * 4);
        float4 vv = *(const float4*)(g_v1 + pos * 32 + n * 4);
        kk = l2n(kk);
        s_k2[cs][idx] = make_ulonglong2(pk2(kk.x, kk.y), pk2(kk.z, kk.w));
        s_v2[cs][idx] = make_ulonglong2(pk2(vv.x, vv.y), pk2(vv.z, vv.w));
    }
    __syncthreads();

    const int cs = t >> 7, tc = t & 127;
    if (tc >= 120) return;
    const int w = w0 + cs;
    const ulonglong2* sk = s_k2[cs];
    const ulonglong2* sv = s_v2[cs];

    const float sc2 = s_sc[0];
    const int posA = tc * IMGW + w, posB = (tc + 120) * IMGW + w;
    unsigned long long qxyA, qzwA, qxyB, qzwB;
    load_q(n, posA, sc2, qxyA, qzwA);
    load_q(n, posB, sc2, qxyB, qzwB);

    float lA = 0.f, lB = 0.f;
    unsigned long long axyA = 0ull, azwA = 0ull, axyB = 0ull, azwB = 0ull;
#pragma unroll 2
    for (int j = 0; j < 240; j++) {
        ulonglong2 kj = sk[j];
        ulonglong2 vj = sv[j];
        float2 sA = upk2(fma2(qzwA, kj.y, mul2(qxyA, kj.x)));
        float2 sB = upk2(fma2(qzwB, kj.y, mul2(qxyB, kj.x)));
        float wA = ex2(sA.x + sA.y);
        float wB = ex2(sB.x + sB.y);
        unsigned long long wwA = pk2(wA, wA);
        unsigned long long wwB = pk2(wB, wB);
        axyA = fma2(wwA, vj.x, axyA);
        azwA = fma2(wwA, vj.y, azwA);
        axyB = fma2(wwB, vj.x, axyB);
        azwB = fma2(wwB, vj.y, azwB);
        lA += wA;
        lB += wB;
    }
    float iA = 1.f / lA, iB = 1.f / lB;
    float2 a01A = upk2(axyA), a23A = upk2(azwA);
    float2 a01B = upk2(axyB), a23B = upk2(azwB);
    const int pair0 = 32 + 2 * n;
    const int pposA = (tc + 1) * PW + (w + 1);
    const int pposB = (tc + 121) * PW + (w + 1);
    store_y_pair(pair0,     pposA, a01A.x * iA, a01A.y * iA);
    store_y_pair(pair0 + 1, pposA, a23A.x * iA, a23A.y * iA);
    store_y_pair(pair0,     pposB, a01B.x * iB, a01B.y * iB);
    store_y_pair(pair0 + 1, pposB, a23B.x * iB, a23B.y * iB);
}

// ---------------------------------------------------------------------------
extern "C" void kernel_launch(void* const* d_in, const int* in_sizes, int n_in,
                              void* d_out, int out_size) {
    const float* x      = (const float*)d_in[0];
    const float* w_in   = (const float*)d_in[1];
    const float* b_in   = (const float*)d_in[2];
    const float* w_f    = (const float*)d_in[3];
    const float* b_f    = (const float*)d_in[4];
    const float* w_out  = (const float*)d_in[5];
    const float* b_out  = (const float*)d_in[6];
    const float* ls     = (const float*)d_in[7];
    const float* lr_ls  = (const float*)d_in[8];
    float* out = (float*)d_out;

    float* p_conv1; unsigned* p_wrep; float* p_bias;
    unsigned *p_xh, *p_xl, *p_yh, *p_yl;
    cudaGetSymbolAddress((void**)&p_conv1, g_conv1);
    cudaGetSymbolAddress((void**)&p_wrep, g_wrep);
    cudaGetSymbolAddress((void**)&p_bias, g_bias);
    cudaGetSymbolAddress((void**)&p_xh, g_xa_hi);
    cudaGetSymbolAddress((void**)&p_xl, g_xa_lo);
    cudaGetSymbolAddress((void**)&p_yh, g_ya_hi);
    cudaGetSymbolAddress((void**)&p_yl, g_ya_lo);

    const int SMEM_BYTES = 20224 * 4;
    static int attr_set = 0;
    if (!attr_set) {
        cudaFuncSetAttribute(conv3x3_mma_kernel,
                             cudaFuncAttributeMaxDynamicSharedMemorySize, SMEM_BYTES);
        attr_set = 1;
    }

    const int NTOT = NPREP_X + NPREP_B + 288 + NREPACK;
    prep_repack_kernel<<<(NTOT + 255) / 256, 256>>>(x, b_in, b_f, w_in, w_f, w_out);

    // fused conv_in+conv_f -> NHWC g_conv1
    conv3x3_mma_kernel<<<dim3(15, 30, 3), 256, SMEM_BYTES>>>(p_xh, p_xl, p_wrep,
                                                             p_bias, p_conv1, 288, 1);

    attn_row_win0_kernel<<<1920 + 2304, 256>>>(ls, lr_ls);
    attn_col_win1_kernel<<<960 + 2304, 256>>>(ls, lr_ls);

    unsigned* wrep_out = p_wrep + 2 * 288 * 432;
    // conv_out -> planar harness output
    conv3x3_mma_kernel<<<dim3(15, 30, 1), 256, SMEM_BYTES>>>(p_yh, p_yl, wrep_out,
                                                             b_out, out, 96, 0);
}